// round 6
// baseline (speedup 1.0000x reference)
#include <cuda_runtime.h>
#include <math.h>

// Problem constants
#define Bb    2
#define NSEQ  2048
#define CDIM  1024
#define HH    8
#define DH    128
#define HALFW 128   // WS/2

// Scratch (device globals: no allocation allowed)
__device__ float g_q[Bb*HH*NSEQ*DH];
__device__ float g_k[Bb*HH*NSEQ*DH];
__device__ float g_v[Bb*HH*NSEQ*DH];
__device__ float g_att[Bb*NSEQ*CDIM];

// ---------------- packed f32x2 helpers (sm_100+) ----------------
static __device__ __forceinline__ unsigned long long pk2(float lo, float hi) {
    unsigned long long r;
    asm("mov.b64 %0, {%1, %2};" : "=l"(r) : "f"(lo), "f"(hi));
    return r;
}
static __device__ __forceinline__ void fma2(unsigned long long& d,
                                            unsigned long long a,
                                            unsigned long long b) {
    asm("fma.rn.f32x2 %0, %1, %2, %0;" : "+l"(d) : "l"(a), "l"(b));
}
static __device__ __forceinline__ void mul2(unsigned long long& d,
                                            unsigned long long a,
                                            unsigned long long b) {
    asm("mul.rn.f32x2 %0, %1, %2;" : "=l"(d) : "l"(a), "l"(b));
}
static __device__ __forceinline__ float2 upk2(unsigned long long v) {
    float lo, hi;
    asm("mov.b64 {%0, %1}, %2;" : "=f"(lo), "=f"(hi) : "l"(v));
    float2 f; f.x = lo; f.y = hi; return f;
}

static __device__ __forceinline__ float neg_inf() {
    return __int_as_float(0xff800000);
}

// ---------------- SGEMM: C[M,Nout] = A[M,K] * B[Nout,K]^T + bias ----------------
// MODE 0: QKV — scatter into g_q/g_k/g_v as [B,H,N,D]
// MODE 1: proj — A is g_att (param ignored), write to Cout
#define BM   128
#define BN   128
#define BKK  8
#define ASTR 132

template <int MODE>
__global__ __launch_bounds__(256, 2)
void sgemm_bt(const float* __restrict__ A,
              const float* __restrict__ Bw,
              const float* __restrict__ bias,
              float* __restrict__ Cout,
              int M, int Nout, int K)
{
    __shared__ float As[BKK][ASTR];
    __shared__ float Bs[BKK][ASTR];

    const int tid = threadIdx.x;
    const int tx = tid & 15;        // 16 column-groups of 8
    const int ty = tid >> 4;        // 16 row-groups of 8
    const int m0 = blockIdx.y * BM;
    const int n0 = blockIdx.x * BN;

    const int lrow  = tid >> 1;       // 0..127
    const int lhalf = (tid & 1) * 4;  // 0 or 4

    const float* Aptr = (MODE == 1) ? (const float*)g_att : A;
    const float* Ap = Aptr + (size_t)(m0 + lrow) * K + lhalf;
    const float* Bp = Bw   + (size_t)(n0 + lrow) * K + lhalf;

    unsigned long long acc[8][4];
#pragma unroll
    for (int i = 0; i < 8; i++)
#pragma unroll
        for (int j = 0; j < 4; j++) acc[i][j] = 0ull;

    // prefetch first k-tile
    float4 av = *(const float4*)(Ap);
    float4 bv = *(const float4*)(Bp);

    for (int k0 = 0; k0 < K; k0 += BKK) {
        __syncthreads();
        As[lhalf + 0][lrow] = av.x; As[lhalf + 1][lrow] = av.y;
        As[lhalf + 2][lrow] = av.z; As[lhalf + 3][lrow] = av.w;
        Bs[lhalf + 0][lrow] = bv.x; Bs[lhalf + 1][lrow] = bv.y;
        Bs[lhalf + 2][lrow] = bv.z; Bs[lhalf + 3][lrow] = bv.w;
        __syncthreads();

        if (k0 + BKK < K) {
            av = *(const float4*)(Ap + k0 + BKK);
            bv = *(const float4*)(Bp + k0 + BKK);
        }

#pragma unroll
        for (int kk = 0; kk < BKK; kk++) {
            float4 a0 = *(const float4*)&As[kk][ty * 8];
            float4 a1 = *(const float4*)&As[kk][ty * 8 + 4];
            float4 b0 = *(const float4*)&Bs[kk][tx * 8];
            float4 b1 = *(const float4*)&Bs[kk][tx * 8 + 4];
            unsigned long long bp0 = pk2(b0.x, b0.y);
            unsigned long long bp1 = pk2(b0.z, b0.w);
            unsigned long long bp2 = pk2(b1.x, b1.y);
            unsigned long long bp3 = pk2(b1.z, b1.w);
            float aa[8] = {a0.x, a0.y, a0.z, a0.w, a1.x, a1.y, a1.z, a1.w};
#pragma unroll
            for (int i = 0; i < 8; i++) {
                unsigned long long ad = pk2(aa[i], aa[i]);
                fma2(acc[i][0], ad, bp0);
                fma2(acc[i][1], ad, bp1);
                fma2(acc[i][2], ad, bp2);
                fma2(acc[i][3], ad, bp3);
            }
        }
    }

    // epilogue
    float bs[8];
#pragma unroll
    for (int j = 0; j < 8; j++) bs[j] = bias[n0 + tx * 8 + j];

    if (MODE == 0) {
        const int t = n0 >> 10;           // which of q/k/v (BN==128 => constant per CTA)
        const int h = (n0 & 1023) >> 7;   // head (constant per CTA)
        float* dst = (t == 0) ? g_q : ((t == 1) ? g_k : g_v);
#pragma unroll
        for (int i = 0; i < 8; i++) {
            int m = m0 + ty * 8 + i;
            int b = m >> 11;        // /NSEQ
            int nn = m & 2047;      // %NSEQ
            float c[8];
#pragma unroll
            for (int jp = 0; jp < 4; jp++) {
                float2 f = upk2(acc[i][jp]);
                c[2 * jp + 0] = f.x + bs[2 * jp + 0];
                c[2 * jp + 1] = f.y + bs[2 * jp + 1];
            }
            size_t off = (((size_t)(b * HH + h)) * NSEQ + nn) * DH + tx * 8;
            float4 w0 = make_float4(c[0], c[1], c[2], c[3]);
            float4 w1 = make_float4(c[4], c[5], c[6], c[7]);
            *(float4*)(dst + off)     = w0;
            *(float4*)(dst + off + 4) = w1;
        }
    } else {
#pragma unroll
        for (int i = 0; i < 8; i++) {
            int m = m0 + ty * 8 + i;
            float c[8];
#pragma unroll
            for (int jp = 0; jp < 4; jp++) {
                float2 f = upk2(acc[i][jp]);
                c[2 * jp + 0] = f.x + bs[2 * jp + 0];
                c[2 * jp + 1] = f.y + bs[2 * jp + 1];
            }
            float* row = Cout + (size_t)m * Nout + n0 + tx * 8;
            *(float4*)(row)     = make_float4(c[0], c[1], c[2], c[3]);
            *(float4*)(row + 4) = make_float4(c[4], c[5], c[6], c[7]);
        }
    }
}

// ---------------- windowed flash attention ----------------
// grid: (NSEQ/64, Bb*HH), 256 threads
// smem: Qs[128][68] (d-major), Ks[128][68] (d-major), Vs[64][132], Ps[64][68]
#define QS_STR 68
#define VS_STR 132
#define SMEM_ATTN ((2 * 128 * QS_STR + 64 * VS_STR + 64 * QS_STR) * 4)

__global__ __launch_bounds__(256)
void attn_win()
{
    extern __shared__ float sm[];
    float* Qs = sm;                                   // [128][68], idx d*68+q
    float* Ks = sm + 128 * QS_STR;                    // [128][68], idx d*68+k
    float* Vs = sm + 2 * 128 * QS_STR;                // [64][132], idx k*132+d
    float* Ps = sm + 2 * 128 * QS_STR + 64 * VS_STR;  // [64][68],  idx q*68+j

    const int tid = threadIdx.x;
    const int tx = tid & 15;   // key-group / out-dim partition
    const int ty = tid >> 4;   // query-group
    const int qb = blockIdx.x;
    const int bh = blockIdx.y;           // b*HH + h
    const int q0 = qb * 64;
    const size_t base = (size_t)bh * NSEQ * DH;
    const float NEGINF = neg_inf();
    const float scale = 1.0f / 32.0f;    // 1/sqrt(C)

    // load Q tile, transposed + scaled
#pragma unroll
    for (int it = 0; it < 8; it++) {
        int g = it * 256 + tid;
        int qr = g & 63, dv = g >> 6;
        float4 v = *(const float4*)(g_q + base + (size_t)(q0 + qr) * DH + dv * 4);
        Qs[(dv * 4 + 0) * QS_STR + qr] = v.x * scale;
        Qs[(dv * 4 + 1) * QS_STR + qr] = v.y * scale;
        Qs[(dv * 4 + 2) * QS_STR + qr] = v.z * scale;
        Qs[(dv * 4 + 3) * QS_STR + qr] = v.w * scale;
    }

    float mrow[4], lsum[4];
    unsigned long long o2[4][4];
#pragma unroll
    for (int i = 0; i < 4; i++) {
        mrow[i] = NEGINF; lsum[i] = 0.0f;
#pragma unroll
        for (int j = 0; j < 4; j++) o2[i][j] = 0ull;
    }

    int lo = q0 - (HALFW - 1); if (lo < 0) lo = 0;
    int hi = q0 + 63 + (HALFW - 1); if (hi > NSEQ - 1) hi = NSEQ - 1;

    for (int kt = lo & ~63; kt <= hi; kt += 64) {
        __syncthreads();
        // K tile, transposed (conflict-free smem stores)
#pragma unroll
        for (int it = 0; it < 8; it++) {
            int g = it * 256 + tid;
            int kr = g & 63, dv = g >> 6;
            int jg = kt + kr;
            float4 v = (jg < NSEQ)
                ? *(const float4*)(g_k + base + (size_t)jg * DH + dv * 4)
                : make_float4(0.f, 0.f, 0.f, 0.f);
            Ks[(dv * 4 + 0) * QS_STR + kr] = v.x;
            Ks[(dv * 4 + 1) * QS_STR + kr] = v.y;
            Ks[(dv * 4 + 2) * QS_STR + kr] = v.z;
            Ks[(dv * 4 + 3) * QS_STR + kr] = v.w;
        }
        // V tile, natural layout (coalesced gmem, contiguous smem stores)
#pragma unroll
        for (int it = 0; it < 8; it++) {
            int g = it * 256 + tid;
            int dv = g & 31, kr = g >> 5;
            int jg = kt + kr;
            float4 v = (jg < NSEQ)
                ? *(const float4*)(g_v + base + (size_t)jg * DH + dv * 4)
                : make_float4(0.f, 0.f, 0.f, 0.f);
            *(float4*)&Vs[kr * VS_STR + dv * 4] = v;
        }
        __syncthreads();

        // S = Q * K^T  (4x4 microtile per thread, packed fp32x2)
        unsigned long long s2[4][2];
#pragma unroll
        for (int i = 0; i < 4; i++) { s2[i][0] = 0ull; s2[i][1] = 0ull; }
#pragma unroll 4
        for (int d = 0; d < 128; d++) {
            float4 a = *(const float4*)&Qs[d * QS_STR + ty * 4];
            float4 b = *(const float4*)&Ks[d * QS_STR + tx * 4];
            unsigned long long bp0 = pk2(b.x, b.y);
            unsigned long long bp1 = pk2(b.z, b.w);
            unsigned long long a0 = pk2(a.x, a.x);
            unsigned long long a1 = pk2(a.y, a.y);
            unsigned long long a2 = pk2(a.z, a.z);
            unsigned long long a3 = pk2(a.w, a.w);
            fma2(s2[0][0], a0, bp0); fma2(s2[0][1], a0, bp1);
            fma2(s2[1][0], a1, bp0); fma2(s2[1][1], a1, bp1);
            fma2(s2[2][0], a2, bp0); fma2(s2[2][1], a2, bp1);
            fma2(s2[3][0], a3, bp0); fma2(s2[3][1], a3, bp1);
        }

        // mask + online softmax (row reductions in 16-lane groups)
#pragma unroll
        for (int i = 0; i < 4; i++) {
            float s[4];
            float2 f0 = upk2(s2[i][0]), f1 = upk2(s2[i][1]);
            s[0] = f0.x; s[1] = f0.y; s[2] = f1.x; s[3] = f1.y;
            int qg = q0 + ty * 4 + i;
#pragma unroll
            for (int j = 0; j < 4; j++) {
                int jg = kt + tx * 4 + j;
                int d = qg - jg; if (d < 0) d = -d;
                if (jg >= NSEQ || d >= HALFW) s[j] = NEGINF;
            }
            float rm = fmaxf(fmaxf(s[0], s[1]), fmaxf(s[2], s[3]));
            rm = fmaxf(rm, __shfl_xor_sync(0xffffffffu, rm, 1));
            rm = fmaxf(rm, __shfl_xor_sync(0xffffffffu, rm, 2));
            rm = fmaxf(rm, __shfl_xor_sync(0xffffffffu, rm, 4));
            rm = fmaxf(rm, __shfl_xor_sync(0xffffffffu, rm, 8));
            float mnew = fmaxf(mrow[i], rm);
            float corr, p[4];
            if (mnew == NEGINF) {
                corr = 1.0f;
                p[0] = p[1] = p[2] = p[3] = 0.0f;
            } else {
                corr = __expf(mrow[i] - mnew);   // mrow=-inf -> 0
#pragma unroll
                for (int j = 0; j < 4; j++) p[j] = __expf(s[j] - mnew); // s=-inf -> 0
            }
            float rs = (p[0] + p[1]) + (p[2] + p[3]);
            rs += __shfl_xor_sync(0xffffffffu, rs, 1);
            rs += __shfl_xor_sync(0xffffffffu, rs, 2);
            rs += __shfl_xor_sync(0xffffffffu, rs, 4);
            rs += __shfl_xor_sync(0xffffffffu, rs, 8);
            lsum[i] = lsum[i] * corr + rs;
            mrow[i] = mnew;
            unsigned long long cd = pk2(corr, corr);
            mul2(o2[i][0], o2[i][0], cd);
            mul2(o2[i][1], o2[i][1], cd);
            mul2(o2[i][2], o2[i][2], cd);
            mul2(o2[i][3], o2[i][3], cd);
            float4 p4 = make_float4(p[0], p[1], p[2], p[3]);
            *(float4*)&Ps[(ty * 4 + i) * QS_STR + tx * 4] = p4;
        }
        __syncthreads();

        // O += P * V  (each thread: 4 q-rows x 8 out-dims at column tx*8)
#pragma unroll 2
        for (int j = 0; j < 64; j++) {
            float4 v0 = *(const float4*)&Vs[j * VS_STR + tx * 8];
            float4 v1 = *(const float4*)&Vs[j * VS_STR + tx * 8 + 4];
            unsigned long long vp0 = pk2(v0.x, v0.y);
            unsigned long long vp1 = pk2(v0.z, v0.w);
            unsigned long long vp2 = pk2(v1.x, v1.y);
            unsigned long long vp3 = pk2(v1.z, v1.w);
#pragma unroll
            for (int i = 0; i < 4; i++) {
                float p = Ps[(ty * 4 + i) * QS_STR + j];
                unsigned long long pd = pk2(p, p);
                fma2(o2[i][0], pd, vp0);
                fma2(o2[i][1], pd, vp1);
                fma2(o2[i][2], pd, vp2);
                fma2(o2[i][3], pd, vp3);
            }
        }
    }

    // epilogue: normalize and write to g_att[b][n][h*DH + d]
    const int b = bh >> 3, h = bh & 7;
#pragma unroll
    for (int i = 0; i < 4; i++) {
        int qg = q0 + ty * 4 + i;
        float inv = 1.0f / lsum[i];
        float c[8];
#pragma unroll
        for (int jp = 0; jp < 4; jp++) {
            float2 f = upk2(o2[i][jp]);
            c[2 * jp + 0] = f.x * inv;
            c[2 * jp + 1] = f.y * inv;
        }
        size_t off = ((size_t)b * NSEQ + qg) * CDIM + h * DH + tx * 8;
        *(float4*)(g_att + off)     = make_float4(c[0], c[1], c[2], c[3]);
        *(float4*)(g_att + off + 4) = make_float4(c[4], c[5], c[6], c[7]);
    }
}

// ---------------- launch ----------------
extern "C" void kernel_launch(void* const* d_in, const int* in_sizes, int n_in,
                              void* d_out, int out_size)
{
    const float* x      = (const float*)d_in[0];
    const float* w_qkv  = (const float*)d_in[1];
    const float* b_qkv  = (const float*)d_in[2];
    const float* w_proj = (const float*)d_in[3];
    const float* b_proj = (const float*)d_in[4];
    float* out = (float*)d_out;

    cudaFuncSetAttribute(attn_win, cudaFuncAttributeMaxDynamicSharedMemorySize,
                         SMEM_ATTN);

    // 1) QKV projection + scatter to [B,H,N,D]
    dim3 g1((3 * CDIM) / BN, (Bb * NSEQ) / BM);   // (24, 32)
    sgemm_bt<0><<<g1, 256>>>(x, w_qkv, b_qkv, nullptr,
                             Bb * NSEQ, 3 * CDIM, CDIM);

    // 2) banded attention -> g_att [B,N,C]
    dim3 g2(NSEQ / 64, Bb * HH);                  // (32, 16)
    attn_win<<<g2, 256, SMEM_ATTN>>>();

    // 3) output projection
    dim3 g3(CDIM / BN, (Bb * NSEQ) / BM);         // (8, 32)
    sgemm_bt<1><<<g3, 256>>>(nullptr, w_proj, b_proj, out,
                             Bb * NSEQ, CDIM, CDIM);
}

// round 9
// speedup vs baseline: 1.8004x; 1.8004x over previous
#include <cuda_runtime.h>
#include <cuda_bf16.h>
#include <math.h>
#include <stdint.h>

// Problem constants
#define Bb    2
#define NSEQ  2048
#define CDIM  1024
#define HH    8
#define DH    128
#define HALFW 128   // WS/2

// Scratch (device globals: no allocation allowed)
__device__ float g_q[Bb*HH*NSEQ*DH];
__device__ float g_k[Bb*HH*NSEQ*DH];
__device__ float g_v[Bb*HH*NSEQ*DH];
__device__ float g_att[Bb*NSEQ*CDIM];

// ================= helpers =================
static __device__ __forceinline__ uint32_t smem_u32(const void* p) {
    uint32_t a;
    asm("{ .reg .u64 t; cvta.to.shared.u64 t, %1; cvt.u32.u64 %0, t; }"
        : "=r"(a) : "l"(p));
    return a;
}

static __device__ __forceinline__ void ldm4(uint32_t* r, uint32_t addr) {
    asm volatile("ldmatrix.sync.aligned.m8n8.x4.shared.b16 {%0,%1,%2,%3}, [%4];"
        : "=r"(r[0]), "=r"(r[1]), "=r"(r[2]), "=r"(r[3]) : "r"(addr));
}

static __device__ __forceinline__ void mma16816(float* d, const uint32_t* a,
                                                uint32_t b0, uint32_t b1) {
    asm volatile(
        "mma.sync.aligned.m16n8k16.row.col.f32.bf16.bf16.f32 "
        "{%0,%1,%2,%3}, {%4,%5,%6,%7}, {%8,%9}, {%0,%1,%2,%3};"
        : "+f"(d[0]), "+f"(d[1]), "+f"(d[2]), "+f"(d[3])
        : "r"(a[0]), "r"(a[1]), "r"(a[2]), "r"(a[3]), "r"(b0), "r"(b1));
}

static __device__ __forceinline__ uint32_t pack2(__nv_bfloat16 a, __nv_bfloat16 b) {
    __nv_bfloat162 t(a, b);              // a -> low half
    return *(uint32_t*)&t;
}

// split float4 into bf16-hi (uint2) and bf16-lo (uint2), k-contiguous packing
static __device__ __forceinline__ void split4(float4 v, uint2& hi, uint2& lo) {
    __nv_bfloat16 hx = __float2bfloat16(v.x);
    __nv_bfloat16 hy = __float2bfloat16(v.y);
    __nv_bfloat16 hz = __float2bfloat16(v.z);
    __nv_bfloat16 hw = __float2bfloat16(v.w);
    float rx = v.x - __bfloat162float(hx);
    float ry = v.y - __bfloat162float(hy);
    float rz = v.z - __bfloat162float(hz);
    float rw = v.w - __bfloat162float(hw);
    hi.x = pack2(hx, hy);
    hi.y = pack2(hz, hw);
    lo.x = pack2(__float2bfloat16(rx), __float2bfloat16(ry));
    lo.y = pack2(__float2bfloat16(rz), __float2bfloat16(rw));
}

// ================= bf16x3 tensor-core GEMM =================
// C[M,Nout] = A[M,K] * B[Nout,K]^T + bias  (fp32-class accuracy, 3x bf16 MMA)
// MODE 0: QKV — scatter into g_q/g_k/g_v [B,H,N,D];  MODE 1: proj -> Cout
#define GBM 128
#define GBN 128
#define GKC 32                 // K elems per chunk (2 k16 steps)
#define ROWB 80                // smem row stride bytes (40 bf16) — conflict-free
#define PL_A_H 0
#define PL_A_L 10240
#define PL_B_H 20480
#define PL_B_L 30720
#define STAGEB 40960
#define SM_STG 1024            // bias lives at [0,512)
#define SMEM_GEMM (SM_STG + 2 * STAGEB)   // 82944 B

template <int MODE>
__global__ __launch_bounds__(256)
void gemm_bf16x3(const float* __restrict__ A,
                 const float* __restrict__ Bw,
                 const float* __restrict__ bias,
                 float* __restrict__ Cout,
                 int K, int Nout)
{
    extern __shared__ char smem[];
    float* sbias = (float*)smem;
    char* stg = smem + SM_STG;
    const uint32_t su = smem_u32(stg);

    const int tid = threadIdx.x;
    const int wid = tid >> 5, lane = tid & 31;
    const int m0 = blockIdx.y * GBM, n0 = blockIdx.x * GBN;
    const int NC = K / GKC;
    const int wm = (wid & 1) * 64;        // warp row offset
    const int wn = (wid >> 1) * 32;       // warp col offset

    if (tid < GBN) sbias[tid] = bias[n0 + tid];

    const float* Abase = ((MODE == 1) ? (const float*)g_att : A) + (size_t)m0 * K;
    const float* Bbase = Bw + (size_t)n0 * K;

    const int lrow = tid >> 3;            // 0..31  (rows lrow, +32, +64, +96)
    const int lcg  = tid & 7;             // k float4-group

    float acc[4][4][4];
#pragma unroll
    for (int i = 0; i < 4; i++)
#pragma unroll
        for (int j = 0; j < 4; j++)
#pragma unroll
            for (int q = 0; q < 4; q++) acc[i][j][q] = 0.0f;

    float4 pa[4], pb[4];
    // prefetch chunk 0
#pragma unroll
    for (int r = 0; r < 4; r++) {
        pa[r] = *(const float4*)(Abase + (size_t)(lrow + 32 * r) * K + lcg * 4);
        pb[r] = *(const float4*)(Bbase + (size_t)(lrow + 32 * r) * K + lcg * 4);
    }
    // store chunk 0 -> stage 0
    {
        char* base = stg;
#pragma unroll
        for (int r = 0; r < 4; r++) {
            int rr = lrow + 32 * r;
            uint2 h, l;
            split4(pa[r], h, l);
            *(uint2*)(base + PL_A_H + rr * ROWB + lcg * 8) = h;
            *(uint2*)(base + PL_A_L + rr * ROWB + lcg * 8) = l;
            split4(pb[r], h, l);
            *(uint2*)(base + PL_B_H + rr * ROWB + lcg * 8) = h;
            *(uint2*)(base + PL_B_L + rr * ROWB + lcg * 8) = l;
        }
    }
    __syncthreads();

    // precomputed ldmatrix lane offsets (bytes within plane, before k offsets)
    const uint32_t a_lrow_off = (uint32_t)(wm + (lane & 15)) * ROWB
                              + ((lane >> 4) << 4);
    const uint32_t b_lrow_off = (uint32_t)(wn + ((lane >> 4) << 3) + (lane & 7)) * ROWB
                              + (((lane >> 3) & 1) << 4);

    for (int c = 0; c < NC; c++) {
        const int s = c & 1;
        const uint32_t sb = su + s * STAGEB;

        if (c + 1 < NC) {
            int kc = (c + 1) * GKC;
#pragma unroll
            for (int r = 0; r < 4; r++) {
                pa[r] = *(const float4*)(Abase + (size_t)(lrow + 32 * r) * K + kc + lcg * 4);
                pb[r] = *(const float4*)(Bbase + (size_t)(lrow + 32 * r) * K + kc + lcg * 4);
            }
        }

#pragma unroll
        for (int ks = 0; ks < 2; ks++) {
            uint32_t ah[4][4], al[4][4];
            uint32_t bh[4][2], bl[4][2];
#pragma unroll
            for (int mt = 0; mt < 4; mt++) {
                uint32_t ad = sb + a_lrow_off + (uint32_t)(mt * 16) * ROWB + ks * 32;
                ldm4(ah[mt], ad + PL_A_H);
                ldm4(al[mt], ad + PL_A_L);
            }
#pragma unroll
            for (int p = 0; p < 2; p++) {
                uint32_t bd = sb + b_lrow_off + (uint32_t)(p * 16) * ROWB + ks * 32;
                uint32_t t[4];
                ldm4(t, bd + PL_B_H);
                bh[2*p][0] = t[0]; bh[2*p][1] = t[1];
                bh[2*p+1][0] = t[2]; bh[2*p+1][1] = t[3];
                ldm4(t, bd + PL_B_L);
                bl[2*p][0] = t[0]; bl[2*p][1] = t[1];
                bl[2*p+1][0] = t[2]; bl[2*p+1][1] = t[3];
            }
#pragma unroll
            for (int mt = 0; mt < 4; mt++)
#pragma unroll
                for (int nt = 0; nt < 4; nt++) {
                    mma16816(acc[mt][nt], ah[mt], bh[nt][0], bh[nt][1]);
                    mma16816(acc[mt][nt], ah[mt], bl[nt][0], bl[nt][1]);
                    mma16816(acc[mt][nt], al[mt], bh[nt][0], bh[nt][1]);
                }
        }

        if (c + 1 < NC) {
            char* base = stg + (s ^ 1) * STAGEB;
#pragma unroll
            for (int r = 0; r < 4; r++) {
                int rr = lrow + 32 * r;
                uint2 h, l;
                split4(pa[r], h, l);
                *(uint2*)(base + PL_A_H + rr * ROWB + lcg * 8) = h;
                *(uint2*)(base + PL_A_L + rr * ROWB + lcg * 8) = l;
                split4(pb[r], h, l);
                *(uint2*)(base + PL_B_H + rr * ROWB + lcg * 8) = h;
                *(uint2*)(base + PL_B_L + rr * ROWB + lcg * 8) = l;
            }
        }
        __syncthreads();
    }

    // epilogue: acc -> gmem (+bias)
    const int t  = n0 >> 10;
    const int hd = (n0 & 1023) >> 7;
    float* dst0 = (t == 0) ? g_q : ((t == 1) ? g_k : g_v);

#pragma unroll
    for (int mt = 0; mt < 4; mt++) {
#pragma unroll
        for (int nt = 0; nt < 4; nt++) {
            float* d = acc[mt][nt];
            int rr = wm + mt * 16 + (lane >> 2);
            int cc = wn + nt * 8 + (lane & 3) * 2;
            float bb0 = sbias[cc], bb1 = sbias[cc + 1];
            int m1 = m0 + rr, m2 = m1 + 8;
            if (MODE == 0) {
                int b1i = m1 >> 11, nn1 = m1 & 2047;
                float2* p1 = (float2*)(dst0 +
                    (((size_t)(b1i * HH + hd)) * NSEQ + nn1) * DH + cc);
                *p1 = make_float2(d[0] + bb0, d[1] + bb1);
                int b2i = m2 >> 11, nn2 = m2 & 2047;
                float2* p2 = (float2*)(dst0 +
                    (((size_t)(b2i * HH + hd)) * NSEQ + nn2) * DH + cc);
                *p2 = make_float2(d[2] + bb0, d[3] + bb1);
            } else {
                float2* p1 = (float2*)(Cout + (size_t)m1 * Nout + n0 + cc);
                *p1 = make_float2(d[0] + bb0, d[1] + bb1);
                float2* p2 = (float2*)(Cout + (size_t)m2 * Nout + n0 + cc);
                *p2 = make_float2(d[2] + bb0, d[3] + bb1);
            }
        }
    }
}

// ---------------- packed f32x2 helpers (attention) ----------------
static __device__ __forceinline__ unsigned long long pk2(float lo, float hi) {
    unsigned long long r;
    asm("mov.b64 %0, {%1, %2};" : "=l"(r) : "f"(lo), "f"(hi));
    return r;
}
static __device__ __forceinline__ void fma2(unsigned long long& d,
                                            unsigned long long a,
                                            unsigned long long b) {
    asm("fma.rn.f32x2 %0, %1, %2, %0;" : "+l"(d) : "l"(a), "l"(b));
}
static __device__ __forceinline__ void mul2(unsigned long long& d,
                                            unsigned long long a,
                                            unsigned long long b) {
    asm("mul.rn.f32x2 %0, %1, %2;" : "=l"(d) : "l"(a), "l"(b));
}
static __device__ __forceinline__ float2 upk2(unsigned long long v) {
    float lo, hi;
    asm("mov.b64 {%0, %1}, %2;" : "=f"(lo), "=f"(hi) : "l"(v));
    float2 f; f.x = lo; f.y = hi; return f;
}
static __device__ __forceinline__ float neg_inf() {
    return __int_as_float(0xff800000);
}

// ---------------- windowed flash attention ----------------
#define QS_STR 68
#define VS_STR 132
#define SMEM_ATTN ((2 * 128 * QS_STR + 64 * VS_STR + 64 * QS_STR) * 4)

__global__ __launch_bounds__(256)
void attn_win()
{
    extern __shared__ float sm[];
    float* Qs = sm;
    float* Ks = sm + 128 * QS_STR;
    float* Vs = sm + 2 * 128 * QS_STR;
    float* Ps = sm + 2 * 128 * QS_STR + 64 * VS_STR;

    const int tid = threadIdx.x;
    const int tx = tid & 15;
    const int ty = tid >> 4;
    const int qb = blockIdx.x;
    const int bh = blockIdx.y;
    const int q0 = qb * 64;
    const size_t base = (size_t)bh * NSEQ * DH;
    const float NEGINF = neg_inf();
    const float scale = 1.0f / 32.0f;

#pragma unroll
    for (int it = 0; it < 8; it++) {
        int g = it * 256 + tid;
        int qr = g & 63, dv = g >> 6;
        float4 v = *(const float4*)(g_q + base + (size_t)(q0 + qr) * DH + dv * 4);
        Qs[(dv * 4 + 0) * QS_STR + qr] = v.x * scale;
        Qs[(dv * 4 + 1) * QS_STR + qr] = v.y * scale;
        Qs[(dv * 4 + 2) * QS_STR + qr] = v.z * scale;
        Qs[(dv * 4 + 3) * QS_STR + qr] = v.w * scale;
    }

    float mrow[4], lsum[4];
    unsigned long long o2[4][4];
#pragma unroll
    for (int i = 0; i < 4; i++) {
        mrow[i] = NEGINF; lsum[i] = 0.0f;
#pragma unroll
        for (int j = 0; j < 4; j++) o2[i][j] = 0ull;
    }

    int lo = q0 - (HALFW - 1); if (lo < 0) lo = 0;
    int hi = q0 + 63 + (HALFW - 1); if (hi > NSEQ - 1) hi = NSEQ - 1;

    for (int kt = lo & ~63; kt <= hi; kt += 64) {
        __syncthreads();
#pragma unroll
        for (int it = 0; it < 8; it++) {
            int g = it * 256 + tid;
            int kr = g & 63, dv = g >> 6;
            int jg = kt + kr;
            float4 v = (jg < NSEQ)
                ? *(const float4*)(g_k + base + (size_t)jg * DH + dv * 4)
                : make_float4(0.f, 0.f, 0.f, 0.f);
            Ks[(dv * 4 + 0) * QS_STR + kr] = v.x;
            Ks[(dv * 4 + 1) * QS_STR + kr] = v.y;
            Ks[(dv * 4 + 2) * QS_STR + kr] = v.z;
            Ks[(dv * 4 + 3) * QS_STR + kr] = v.w;
        }
#pragma unroll
        for (int it = 0; it < 8; it++) {
            int g = it * 256 + tid;
            int dv = g & 31, kr = g >> 5;
            int jg = kt + kr;
            float4 v = (jg < NSEQ)
                ? *(const float4*)(g_v + base + (size_t)jg * DH + dv * 4)
                : make_float4(0.f, 0.f, 0.f, 0.f);
            *(float4*)&Vs[kr * VS_STR + dv * 4] = v;
        }
        __syncthreads();

        unsigned long long s2[4][2];
#pragma unroll
        for (int i = 0; i < 4; i++) { s2[i][0] = 0ull; s2[i][1] = 0ull; }
#pragma unroll 4
        for (int d = 0; d < 128; d++) {
            float4 a = *(const float4*)&Qs[d * QS_STR + ty * 4];
            float4 b = *(const float4*)&Ks[d * QS_STR + tx * 4];
            unsigned long long bp0 = pk2(b.x, b.y);
            unsigned long long bp1 = pk2(b.z, b.w);
            unsigned long long a0 = pk2(a.x, a.x);
            unsigned long long a1 = pk2(a.y, a.y);
            unsigned long long a2 = pk2(a.z, a.z);
            unsigned long long a3 = pk2(a.w, a.w);
            fma2(s2[0][0], a0, bp0); fma2(s2[0][1], a0, bp1);
            fma2(s2[1][0], a1, bp0); fma2(s2[1][1], a1, bp1);
            fma2(s2[2][0], a2, bp0); fma2(s2[2][1], a2, bp1);
            fma2(s2[3][0], a3, bp0); fma2(s2[3][1], a3, bp1);
        }

#pragma unroll
        for (int i = 0; i < 4; i++) {
            float s[4];
            float2 f0 = upk2(s2[i][0]), f1 = upk2(s2[i][1]);
            s[0] = f0.x; s[1] = f0.y; s[2] = f1.x; s[3] = f1.y;
            int qg = q0 + ty * 4 + i;
#pragma unroll
            for (int j = 0; j < 4; j++) {
                int jg = kt + tx * 4 + j;
                int d = qg - jg; if (d < 0) d = -d;
                if (jg >= NSEQ || d >= HALFW) s[j] = NEGINF;
            }
            float rm = fmaxf(fmaxf(s[0], s[1]), fmaxf(s[2], s[3]));
            rm = fmaxf(rm, __shfl_xor_sync(0xffffffffu, rm, 1));
            rm = fmaxf(rm, __shfl_xor_sync(0xffffffffu, rm, 2));
            rm = fmaxf(rm, __shfl_xor_sync(0xffffffffu, rm, 4));
            rm = fmaxf(rm, __shfl_xor_sync(0xffffffffu, rm, 8));
            float mnew = fmaxf(mrow[i], rm);
            float corr, p[4];
            if (mnew == NEGINF) {
                corr = 1.0f;
                p[0] = p[1] = p[2] = p[3] = 0.0f;
            } else {
                corr = __expf(mrow[i] - mnew);
#pragma unroll
                for (int j = 0; j < 4; j++) p[j] = __expf(s[j] - mnew);
            }
            float rs = (p[0] + p[1]) + (p[2] + p[3]);
            rs += __shfl_xor_sync(0xffffffffu, rs, 1);
            rs += __shfl_xor_sync(0xffffffffu, rs, 2);
            rs += __shfl_xor_sync(0xffffffffu, rs, 4);
            rs += __shfl_xor_sync(0xffffffffu, rs, 8);
            lsum[i] = lsum[i] * corr + rs;
            mrow[i] = mnew;
            unsigned long long cd = pk2(corr, corr);
            mul2(o2[i][0], o2[i][0], cd);
            mul2(o2[i][1], o2[i][1], cd);
            mul2(o2[i][2], o2[i][2], cd);
            mul2(o2[i][3], o2[i][3], cd);
            float4 p4 = make_float4(p[0], p[1], p[2], p[3]);
            *(float4*)&Ps[(ty * 4 + i) * QS_STR + tx * 4] = p4;
        }
        __syncthreads();

#pragma unroll 2
        for (int j = 0; j < 64; j++) {
            float4 v0 = *(const float4*)&Vs[j * VS_STR + tx * 8];
            float4 v1 = *(const float4*)&Vs[j * VS_STR + tx * 8 + 4];
            unsigned long long vp0 = pk2(v0.x, v0.y);
            unsigned long long vp1 = pk2(v0.z, v0.w);
            unsigned long long vp2 = pk2(v1.x, v1.y);
            unsigned long long vp3 = pk2(v1.z, v1.w);
#pragma unroll
            for (int i = 0; i < 4; i++) {
                float p = Ps[(ty * 4 + i) * QS_STR + j];
                unsigned long long pd = pk2(p, p);
                fma2(o2[i][0], pd, vp0);
                fma2(o2[i][1], pd, vp1);
                fma2(o2[i][2], pd, vp2);
                fma2(o2[i][3], pd, vp3);
            }
        }
    }

    const int b = bh >> 3, h = bh & 7;
#pragma unroll
    for (int i = 0; i < 4; i++) {
        int qg = q0 + ty * 4 + i;
        float inv = 1.0f / lsum[i];
        float c[8];
#pragma unroll
        for (int jp = 0; jp < 4; jp++) {
            float2 f = upk2(o2[i][jp]);
            c[2 * jp + 0] = f.x * inv;
            c[2 * jp + 1] = f.y * inv;
        }
        size_t off = ((size_t)b * NSEQ + qg) * CDIM + h * DH + tx * 8;
        *(float4*)(g_att + off)     = make_float4(c[0], c[1], c[2], c[3]);
        *(float4*)(g_att + off + 4) = make_float4(c[4], c[5], c[6], c[7]);
    }
}

// ---------------- launch ----------------
extern "C" void kernel_launch(void* const* d_in, const int* in_sizes, int n_in,
                              void* d_out, int out_size)
{
    const float* x      = (const float*)d_in[0];
    const float* w_qkv  = (const float*)d_in[1];
    const float* b_qkv  = (const float*)d_in[2];
    const float* w_proj = (const float*)d_in[3];
    const float* b_proj = (const float*)d_in[4];
    float* out = (float*)d_out;

    cudaFuncSetAttribute(gemm_bf16x3<0>,
                         cudaFuncAttributeMaxDynamicSharedMemorySize, SMEM_GEMM);
    cudaFuncSetAttribute(gemm_bf16x3<1>,
                         cudaFuncAttributeMaxDynamicSharedMemorySize, SMEM_GEMM);
    cudaFuncSetAttribute(attn_win,
                         cudaFuncAttributeMaxDynamicSharedMemorySize, SMEM_ATTN);

    // 1) QKV projection (bf16x3 tensor core) + scatter to [B,H,N,D]
    dim3 g1((3 * CDIM) / GBN, (Bb * NSEQ) / GBM);   // (24, 32)
    gemm_bf16x3<0><<<g1, 256, SMEM_GEMM>>>(x, w_qkv, b_qkv, nullptr,
                                           CDIM, 3 * CDIM);

    // 2) banded attention -> g_att [B,N,C]
    dim3 g2(NSEQ / 64, Bb * HH);                    // (32, 16)
    attn_win<<<g2, 256, SMEM_ATTN>>>();

    // 3) output projection (bf16x3 tensor core)
    dim3 g3(CDIM / GBN, (Bb * NSEQ) / GBM);         // (8, 32)
    gemm_bf16x3<1><<<g3, 256, SMEM_GEMM>>>(nullptr, w_proj, b_proj, out,
                                           CDIM, CDIM);
}

// round 12
// speedup vs baseline: 1.9867x; 1.1034x over previous
#include <cuda_runtime.h>
#include <cuda_bf16.h>
#include <math.h>
#include <stdint.h>

// Problem constants
#define Bb    2
#define NSEQ  2048
#define CDIM  1024
#define HH    8
#define DH    128
#define HALFW 128   // WS/2

// Scratch (device globals: no allocation allowed)
__device__ float g_q[Bb*HH*NSEQ*DH];
__device__ float g_k[Bb*HH*NSEQ*DH];
__device__ float g_v[Bb*HH*NSEQ*DH];

// bf16 hi/lo planes (pre-split operands for tensor-core GEMMs)
__device__ __nv_bfloat16 g_xh[Bb*NSEQ*CDIM],  g_xl[Bb*NSEQ*CDIM];
__device__ __nv_bfloat16 g_wqh[3*CDIM*CDIM],  g_wql[3*CDIM*CDIM];
__device__ __nv_bfloat16 g_wph[CDIM*CDIM],    g_wpl[CDIM*CDIM];
__device__ __nv_bfloat16 g_atth[Bb*NSEQ*CDIM], g_attl[Bb*NSEQ*CDIM];

// ================= helpers =================
static __device__ __forceinline__ uint32_t smem_u32(const void* p) {
    uint32_t a;
    asm("{ .reg .u64 t; cvta.to.shared.u64 t, %1; cvt.u32.u64 %0, t; }"
        : "=r"(a) : "l"(p));
    return a;
}

static __device__ __forceinline__ void ldm4(uint32_t* r, uint32_t addr) {
    asm volatile("ldmatrix.sync.aligned.m8n8.x4.shared.b16 {%0,%1,%2,%3}, [%4];"
        : "=r"(r[0]), "=r"(r[1]), "=r"(r[2]), "=r"(r[3]) : "r"(addr));
}

static __device__ __forceinline__ void mma16816(float* d, const uint32_t* a,
                                                uint32_t b0, uint32_t b1) {
    asm volatile(
        "mma.sync.aligned.m16n8k16.row.col.f32.bf16.bf16.f32 "
        "{%0,%1,%2,%3}, {%4,%5,%6,%7}, {%8,%9}, {%0,%1,%2,%3};"
        : "+f"(d[0]), "+f"(d[1]), "+f"(d[2]), "+f"(d[3])
        : "r"(a[0]), "r"(a[1]), "r"(a[2]), "r"(a[3]), "r"(b0), "r"(b1));
}

static __device__ __forceinline__ uint32_t pack2(__nv_bfloat16 a, __nv_bfloat16 b) {
    __nv_bfloat162 t(a, b);              // a -> low half
    return *(uint32_t*)&t;
}

// split float4 into bf16-hi (uint2) and bf16-lo (uint2), k-contiguous packing
static __device__ __forceinline__ void split4(float4 v, uint2& hi, uint2& lo) {
    __nv_bfloat16 hx = __float2bfloat16(v.x);
    __nv_bfloat16 hy = __float2bfloat16(v.y);
    __nv_bfloat16 hz = __float2bfloat16(v.z);
    __nv_bfloat16 hw = __float2bfloat16(v.w);
    float rx = v.x - __bfloat162float(hx);
    float ry = v.y - __bfloat162float(hy);
    float rz = v.z - __bfloat162float(hz);
    float rw = v.w - __bfloat162float(hw);
    hi.x = pack2(hx, hy);
    hi.y = pack2(hz, hw);
    lo.x = pack2(__float2bfloat16(rx), __float2bfloat16(ry));
    lo.y = pack2(__float2bfloat16(rz), __float2bfloat16(rw));
}

// ================= pre-pass: split float arrays into bf16 hi/lo planes =====
template <int SEL>
__global__ __launch_bounds__(256)
void split_planes(const float* __restrict__ src, int n4)
{
    __nv_bfloat16* h = (SEL == 0) ? g_xh : ((SEL == 1) ? g_wqh : g_wph);
    __nv_bfloat16* l = (SEL == 0) ? g_xl : ((SEL == 1) ? g_wql : g_wpl);
    int i = blockIdx.x * 256 + threadIdx.x;
    if (i < n4) {
        float4 v = ((const float4*)src)[i];
        uint2 hh, ll;
        split4(v, hh, ll);
        ((uint2*)h)[i] = hh;
        ((uint2*)l)[i] = ll;
    }
}

// ================= bf16x3 tensor-core GEMM (cp.async, pre-split planes) ====
// C[M,Nout] = A[M,K] * B[Nout,K]^T + bias
// MODE 0: A=x planes, B=w_qkv planes -> scatter g_q/g_k/g_v [B,H,N,D]
// MODE 1: A=g_att planes, B=w_proj planes -> Cout
#define GBM 128
#define GBN 128
#define GKC 32                 // K elems per chunk (2 k16 steps)
#define ROWB 80                // smem row stride bytes — conflict-free ldmatrix
#define PLANEB 10240           // 128 rows * 80 B
#define STAGEB 40960           // 4 planes
#define SM_STG 1024            // bias at [0,512)
#define SMEM_GEMM (SM_STG + 2 * STAGEB)   // 82944 B

template <int MODE>
__global__ __launch_bounds__(256, 2)
void gemm_bf16x3(const float* __restrict__ bias,
                 float* __restrict__ Cout,
                 int K, int Nout)
{
    extern __shared__ char smem[];
    float* sbias = (float*)smem;
    char* stg = smem + SM_STG;
    const uint32_t su = smem_u32(stg);

    const int tid = threadIdx.x;
    const int wid = tid >> 5, lane = tid & 31;
    const int m0 = blockIdx.y * GBM, n0 = blockIdx.x * GBN;
    const int NC = K / GKC;
    const int wm = (wid & 1) * 64;
    const int wn = (wid >> 1) * 32;

    if (tid < GBN) sbias[tid] = bias[n0 + tid];

    const __nv_bfloat16* pb[4];
    if (MODE == 0) {
        pb[0] = g_xh  + (size_t)m0 * K;
        pb[1] = g_xl  + (size_t)m0 * K;
        pb[2] = g_wqh + (size_t)n0 * K;
        pb[3] = g_wql + (size_t)n0 * K;
    } else {
        pb[0] = g_atth + (size_t)m0 * K;
        pb[1] = g_attl + (size_t)m0 * K;
        pb[2] = g_wph  + (size_t)n0 * K;
        pb[3] = g_wpl  + (size_t)n0 * K;
    }

    const int r0  = tid >> 2;     // 0..63 (rows r0 and r0+64)
    const int c16 = tid & 3;      // 16B chunk within 64B row

    auto issue = [&](int kc, int s) {
        uint32_t sb = su + s * STAGEB;
#pragma unroll
        for (int p = 0; p < 4; p++) {
#pragma unroll
            for (int hh = 0; hh < 2; hh++) {
                int r = r0 + hh * 64;
                const void* src = pb[p] + (size_t)r * K + kc + c16 * 8;
                uint32_t dst = sb + p * PLANEB + r * ROWB + c16 * 16;
                asm volatile("cp.async.cg.shared.global [%0], [%1], 16;"
                             :: "r"(dst), "l"(src));
            }
        }
        asm volatile("cp.async.commit_group;" ::: "memory");
    };

    float acc[4][4][4];
#pragma unroll
    for (int i = 0; i < 4; i++)
#pragma unroll
        for (int j = 0; j < 4; j++)
#pragma unroll
            for (int q = 0; q < 4; q++) acc[i][j][q] = 0.0f;

    issue(0, 0);
    issue(GKC, 1);

    // ldmatrix lane offsets (bytes within plane, before k offset)
    const uint32_t a_lrow_off = (uint32_t)(wm + (lane & 15)) * ROWB
                              + ((lane >> 4) << 4);
    const uint32_t b_lrow_off = (uint32_t)(wn + ((lane >> 4) << 3) + (lane & 7)) * ROWB
                              + (((lane >> 3) & 1) << 4);

    for (int c = 0; c < NC; c++) {
        if (c + 1 < NC)
            asm volatile("cp.async.wait_group 1;" ::: "memory");
        else
            asm volatile("cp.async.wait_group 0;" ::: "memory");
        __syncthreads();

        const uint32_t sb = su + (c & 1) * STAGEB;

#pragma unroll
        for (int ks = 0; ks < 2; ks++) {
            uint32_t ah[4][4], al[4][4];
            uint32_t bh[4][2], bl[4][2];
#pragma unroll
            for (int mt = 0; mt < 4; mt++) {
                uint32_t ad = sb + a_lrow_off + (uint32_t)(mt * 16) * ROWB + ks * 32;
                ldm4(ah[mt], ad + 0 * PLANEB);
                ldm4(al[mt], ad + 1 * PLANEB);
            }
#pragma unroll
            for (int p = 0; p < 2; p++) {
                uint32_t bd = sb + b_lrow_off + (uint32_t)(p * 16) * ROWB + ks * 32;
                uint32_t t[4];
                ldm4(t, bd + 2 * PLANEB);
                bh[2*p][0] = t[0]; bh[2*p][1] = t[1];
                bh[2*p+1][0] = t[2]; bh[2*p+1][1] = t[3];
                ldm4(t, bd + 3 * PLANEB);
                bl[2*p][0] = t[0]; bl[2*p][1] = t[1];
                bl[2*p+1][0] = t[2]; bl[2*p+1][1] = t[3];
            }
#pragma unroll
            for (int mt = 0; mt < 4; mt++)
#pragma unroll
                for (int nt = 0; nt < 4; nt++) {
                    mma16816(acc[mt][nt], ah[mt], bh[nt][0], bh[nt][1]);
                    mma16816(acc[mt][nt], ah[mt], bl[nt][0], bl[nt][1]);
                    mma16816(acc[mt][nt], al[mt], bh[nt][0], bh[nt][1]);
                }
        }
        __syncthreads();
        if (c + 2 < NC) issue((c + 2) * GKC, c & 1);
    }

    // epilogue: acc -> gmem (+bias)
    const int t  = n0 >> 10;
    const int hd = (n0 & 1023) >> 7;
    float* dst0 = (t == 0) ? g_q : ((t == 1) ? g_k : g_v);

#pragma unroll
    for (int mt = 0; mt < 4; mt++) {
#pragma unroll
        for (int nt = 0; nt < 4; nt++) {
            float* d = acc[mt][nt];
            int rr = wm + mt * 16 + (lane >> 2);
            int cc = wn + nt * 8 + (lane & 3) * 2;
            float bb0 = sbias[cc], bb1 = sbias[cc + 1];
            int m1 = m0 + rr, m2 = m1 + 8;
            if (MODE == 0) {
                int b1i = m1 >> 11, nn1 = m1 & 2047;
                float2* p1 = (float2*)(dst0 +
                    (((size_t)(b1i * HH + hd)) * NSEQ + nn1) * DH + cc);
                *p1 = make_float2(d[0] + bb0, d[1] + bb1);
                int b2i = m2 >> 11, nn2 = m2 & 2047;
                float2* p2 = (float2*)(dst0 +
                    (((size_t)(b2i * HH + hd)) * NSEQ + nn2) * DH + cc);
                *p2 = make_float2(d[2] + bb0, d[3] + bb1);
            } else {
                float2* p1 = (float2*)(Cout + (size_t)m1 * Nout + n0 + cc);
                *p1 = make_float2(d[0] + bb0, d[1] + bb1);
                float2* p2 = (float2*)(Cout + (size_t)m2 * Nout + n0 + cc);
                *p2 = make_float2(d[2] + bb0, d[3] + bb1);
            }
        }
    }
}

// ---------------- packed f32x2 helpers (attention) ----------------
static __device__ __forceinline__ unsigned long long pk2(float lo, float hi) {
    unsigned long long r;
    asm("mov.b64 %0, {%1, %2};" : "=l"(r) : "f"(lo), "f"(hi));
    return r;
}
static __device__ __forceinline__ void fma2(unsigned long long& d,
                                            unsigned long long a,
                                            unsigned long long b) {
    asm("fma.rn.f32x2 %0, %1, %2, %0;" : "+l"(d) : "l"(a), "l"(b));
}
static __device__ __forceinline__ void mul2(unsigned long long& d,
                                            unsigned long long a,
                                            unsigned long long b) {
    asm("mul.rn.f32x2 %0, %1, %2;" : "=l"(d) : "l"(a), "l"(b));
}
static __device__ __forceinline__ float2 upk2(unsigned long long v) {
    float lo, hi;
    asm("mov.b64 {%0, %1}, %2;" : "=f"(lo), "=f"(hi) : "l"(v));
    float2 f; f.x = lo; f.y = hi; return f;
}
static __device__ __forceinline__ float neg_inf() {
    return __int_as_float(0xff800000);
}

// ---------------- windowed flash attention ----------------
#define QS_STR 68
#define VS_STR 132
#define SMEM_ATTN ((2 * 128 * QS_STR + 64 * VS_STR + 64 * QS_STR) * 4)

__global__ __launch_bounds__(256)
void attn_win()
{
    extern __shared__ float sm[];
    float* Qs = sm;
    float* Ks = sm + 128 * QS_STR;
    float* Vs = sm + 2 * 128 * QS_STR;
    float* Ps = sm + 2 * 128 * QS_STR + 64 * VS_STR;

    const int tid = threadIdx.x;
    const int tx = tid & 15;
    const int ty = tid >> 4;
    const int qb = blockIdx.x;
    const int bh = blockIdx.y;
    const int q0 = qb * 64;
    const size_t base = (size_t)bh * NSEQ * DH;
    const float NEGINF = neg_inf();
    const float scale = 1.0f / 32.0f;

#pragma unroll
    for (int it = 0; it < 8; it++) {
        int g = it * 256 + tid;
        int qr = g & 63, dv = g >> 6;
        float4 v = *(const float4*)(g_q + base + (size_t)(q0 + qr) * DH + dv * 4);
        Qs[(dv * 4 + 0) * QS_STR + qr] = v.x * scale;
        Qs[(dv * 4 + 1) * QS_STR + qr] = v.y * scale;
        Qs[(dv * 4 + 2) * QS_STR + qr] = v.z * scale;
        Qs[(dv * 4 + 3) * QS_STR + qr] = v.w * scale;
    }

    float mrow[4], lsum[4];
    unsigned long long o2[4][4];
#pragma unroll
    for (int i = 0; i < 4; i++) {
        mrow[i] = NEGINF; lsum[i] = 0.0f;
#pragma unroll
        for (int j = 0; j < 4; j++) o2[i][j] = 0ull;
    }

    int lo = q0 - (HALFW - 1); if (lo < 0) lo = 0;
    int hi = q0 + 63 + (HALFW - 1); if (hi > NSEQ - 1) hi = NSEQ - 1;

    for (int kt = lo & ~63; kt <= hi; kt += 64) {
        __syncthreads();
#pragma unroll
        for (int it = 0; it < 8; it++) {
            int g = it * 256 + tid;
            int kr = g & 63, dv = g >> 6;
            int jg = kt + kr;
            float4 v = (jg < NSEQ)
                ? *(const float4*)(g_k + base + (size_t)jg * DH + dv * 4)
                : make_float4(0.f, 0.f, 0.f, 0.f);
            Ks[(dv * 4 + 0) * QS_STR + kr] = v.x;
            Ks[(dv * 4 + 1) * QS_STR + kr] = v.y;
            Ks[(dv * 4 + 2) * QS_STR + kr] = v.z;
            Ks[(dv * 4 + 3) * QS_STR + kr] = v.w;
        }
#pragma unroll
        for (int it = 0; it < 8; it++) {
            int g = it * 256 + tid;
            int dv = g & 31, kr = g >> 5;
            int jg = kt + kr;
            float4 v = (jg < NSEQ)
                ? *(const float4*)(g_v + base + (size_t)jg * DH + dv * 4)
                : make_float4(0.f, 0.f, 0.f, 0.f);
            *(float4*)&Vs[kr * VS_STR + dv * 4] = v;
        }
        __syncthreads();

        unsigned long long s2[4][2];
#pragma unroll
        for (int i = 0; i < 4; i++) { s2[i][0] = 0ull; s2[i][1] = 0ull; }
#pragma unroll 4
        for (int d = 0; d < 128; d++) {
            float4 a = *(const float4*)&Qs[d * QS_STR + ty * 4];
            float4 b = *(const float4*)&Ks[d * QS_STR + tx * 4];
            unsigned long long bp0 = pk2(b.x, b.y);
            unsigned long long bp1 = pk2(b.z, b.w);
            unsigned long long a0 = pk2(a.x, a.x);
            unsigned long long a1 = pk2(a.y, a.y);
            unsigned long long a2 = pk2(a.z, a.z);
            unsigned long long a3 = pk2(a.w, a.w);
            fma2(s2[0][0], a0, bp0); fma2(s2[0][1], a0, bp1);
            fma2(s2[1][0], a1, bp0); fma2(s2[1][1], a1, bp1);
            fma2(s2[2][0], a2, bp0); fma2(s2[2][1], a2, bp1);
            fma2(s2[3][0], a3, bp0); fma2(s2[3][1], a3, bp1);
        }

#pragma unroll
        for (int i = 0; i < 4; i++) {
            float s[4];
            float2 f0 = upk2(s2[i][0]), f1 = upk2(s2[i][1]);
            s[0] = f0.x; s[1] = f0.y; s[2] = f1.x; s[3] = f1.y;
            int qg = q0 + ty * 4 + i;
#pragma unroll
            for (int j = 0; j < 4; j++) {
                int jg = kt + tx * 4 + j;
                int d = qg - jg; if (d < 0) d = -d;
                if (jg >= NSEQ || d >= HALFW) s[j] = NEGINF;
            }
            float rm = fmaxf(fmaxf(s[0], s[1]), fmaxf(s[2], s[3]));
            rm = fmaxf(rm, __shfl_xor_sync(0xffffffffu, rm, 1));
            rm = fmaxf(rm, __shfl_xor_sync(0xffffffffu, rm, 2));
            rm = fmaxf(rm, __shfl_xor_sync(0xffffffffu, rm, 4));
            rm = fmaxf(rm, __shfl_xor_sync(0xffffffffu, rm, 8));
            float mnew = fmaxf(mrow[i], rm);
            float corr, p[4];
            if (mnew == NEGINF) {
                corr = 1.0f;
                p[0] = p[1] = p[2] = p[3] = 0.0f;
            } else {
                corr = __expf(mrow[i] - mnew);
#pragma unroll
                for (int j = 0; j < 4; j++) p[j] = __expf(s[j] - mnew);
            }
            float rs = (p[0] + p[1]) + (p[2] + p[3]);
            rs += __shfl_xor_sync(0xffffffffu, rs, 1);
            rs += __shfl_xor_sync(0xffffffffu, rs, 2);
            rs += __shfl_xor_sync(0xffffffffu, rs, 4);
            rs += __shfl_xor_sync(0xffffffffu, rs, 8);
            lsum[i] = lsum[i] * corr + rs;
            mrow[i] = mnew;
            unsigned long long cd = pk2(corr, corr);
            mul2(o2[i][0], o2[i][0], cd);
            mul2(o2[i][1], o2[i][1], cd);
            mul2(o2[i][2], o2[i][2], cd);
            mul2(o2[i][3], o2[i][3], cd);
            float4 p4 = make_float4(p[0], p[1], p[2], p[3]);
            *(float4*)&Ps[(ty * 4 + i) * QS_STR + tx * 4] = p4;
        }
        __syncthreads();

#pragma unroll 2
        for (int j = 0; j < 64; j++) {
            float4 v0 = *(const float4*)&Vs[j * VS_STR + tx * 8];
            float4 v1 = *(const float4*)&Vs[j * VS_STR + tx * 8 + 4];
            unsigned long long vp0 = pk2(v0.x, v0.y);
            unsigned long long vp1 = pk2(v0.z, v0.w);
            unsigned long long vp2 = pk2(v1.x, v1.y);
            unsigned long long vp3 = pk2(v1.z, v1.w);
#pragma unroll
            for (int i = 0; i < 4; i++) {
                float p = Ps[(ty * 4 + i) * QS_STR + j];
                unsigned long long pd = pk2(p, p);
                fma2(o2[i][0], pd, vp0);
                fma2(o2[i][1], pd, vp1);
                fma2(o2[i][2], pd, vp2);
                fma2(o2[i][3], pd, vp3);
            }
        }
    }

    // epilogue: normalize, split to bf16 hi/lo planes for the proj GEMM
    const int b = bh >> 3, h = bh & 7;
#pragma unroll
    for (int i = 0; i < 4; i++) {
        int qg = q0 + ty * 4 + i;
        float inv = 1.0f / lsum[i];
        float c[8];
#pragma unroll
        for (int jp = 0; jp < 4; jp++) {
            float2 f = upk2(o2[i][jp]);
            c[2 * jp + 0] = f.x * inv;
            c[2 * jp + 1] = f.y * inv;
        }
        float4 f0 = make_float4(c[0], c[1], c[2], c[3]);
        float4 f1 = make_float4(c[4], c[5], c[6], c[7]);
        uint2 h0, l0, h1, l1;
        split4(f0, h0, l0);
        split4(f1, h1, l1);
        size_t off = ((size_t)b * NSEQ + qg) * CDIM + h * DH + tx * 8;
        *(uint4*)((char*)g_atth + off * 2) = make_uint4(h0.x, h0.y, h1.x, h1.y);
        *(uint4*)((char*)g_attl + off * 2) = make_uint4(l0.x, l0.y, l1.x, l1.y);
    }
}

// ---------------- launch ----------------
extern "C" void kernel_launch(void* const* d_in, const int* in_sizes, int n_in,
                              void* d_out, int out_size)
{
    const float* x      = (const float*)d_in[0];
    const float* w_qkv  = (const float*)d_in[1];
    const float* b_qkv  = (const float*)d_in[2];
    const float* w_proj = (const float*)d_in[3];
    const float* b_proj = (const float*)d_in[4];
    float* out = (float*)d_out;

    cudaFuncSetAttribute(gemm_bf16x3<0>,
                         cudaFuncAttributeMaxDynamicSharedMemorySize, SMEM_GEMM);
    cudaFuncSetAttribute(gemm_bf16x3<1>,
                         cudaFuncAttributeMaxDynamicSharedMemorySize, SMEM_GEMM);
    cudaFuncSetAttribute(attn_win,
                         cudaFuncAttributeMaxDynamicSharedMemorySize, SMEM_ATTN);

    // 0) split inputs into bf16 hi/lo planes
    {
        int n4x = (Bb * NSEQ * CDIM) / 4;       // 1048576
        int n4q = (3 * CDIM * CDIM) / 4;        // 786432
        int n4p = (CDIM * CDIM) / 4;            // 262144
        split_planes<0><<<(n4x + 255) / 256, 256>>>(x, n4x);
        split_planes<1><<<(n4q + 255) / 256, 256>>>(w_qkv, n4q);
        split_planes<2><<<(n4p + 255) / 256, 256>>>(w_proj, n4p);
    }

    // 1) QKV projection (bf16x3 HMMA + cp.async) -> scatter [B,H,N,D]
    dim3 g1((3 * CDIM) / GBN, (Bb * NSEQ) / GBM);   // (24, 32)
    gemm_bf16x3<0><<<g1, 256, SMEM_GEMM>>>(b_qkv, nullptr, CDIM, 3 * CDIM);

    // 2) banded attention -> g_atth/g_attl planes
    dim3 g2(NSEQ / 64, Bb * HH);                    // (32, 16)
    attn_win<<<g2, 256, SMEM_ATTN>>>();

    // 3) output projection
    dim3 g3(CDIM / GBN, (Bb * NSEQ) / GBM);         // (8, 32)
    gemm_bf16x3<1><<<g3, 256, SMEM_GEMM>>>(b_proj, out, CDIM, CDIM);
}

// round 13
// speedup vs baseline: 2.6591x; 1.3385x over previous
#include <cuda_runtime.h>
#include <cuda_bf16.h>
#include <math.h>
#include <stdint.h>

// Problem constants
#define Bb    2
#define NSEQ  2048
#define CDIM  1024
#define HH    8
#define DH    128
#define HALFW 128   // WS/2

// bf16 hi/lo planes (device globals — no allocation allowed)
__device__ __nv_bfloat16 g_xh[Bb*NSEQ*CDIM],  g_xl[Bb*NSEQ*CDIM];
__device__ __nv_bfloat16 g_wqh[3*CDIM*CDIM],  g_wql[3*CDIM*CDIM];
__device__ __nv_bfloat16 g_wph[CDIM*CDIM],    g_wpl[CDIM*CDIM];
__device__ __nv_bfloat16 g_atth[Bb*NSEQ*CDIM], g_attl[Bb*NSEQ*CDIM];
// q/k/v planes, [B,H,N,D]; q pre-scaled by 1/32
__device__ __nv_bfloat16 g_qh[Bb*HH*NSEQ*DH], g_ql[Bb*HH*NSEQ*DH];
__device__ __nv_bfloat16 g_kh[Bb*HH*NSEQ*DH], g_kl[Bb*HH*NSEQ*DH];
__device__ __nv_bfloat16 g_vh[Bb*HH*NSEQ*DH], g_vl[Bb*HH*NSEQ*DH];

// ================= helpers =================
static __device__ __forceinline__ uint32_t smem_u32(const void* p) {
    uint32_t a;
    asm("{ .reg .u64 t; cvta.to.shared.u64 t, %1; cvt.u32.u64 %0, t; }"
        : "=r"(a) : "l"(p));
    return a;
}
static __device__ __forceinline__ void cp16(uint32_t dst, const void* src) {
    asm volatile("cp.async.cg.shared.global [%0], [%1], 16;"
                 :: "r"(dst), "l"(src));
}
static __device__ __forceinline__ void ldm4(uint32_t* r, uint32_t addr) {
    asm volatile("ldmatrix.sync.aligned.m8n8.x4.shared.b16 {%0,%1,%2,%3}, [%4];"
        : "=r"(r[0]), "=r"(r[1]), "=r"(r[2]), "=r"(r[3]) : "r"(addr));
}
static __device__ __forceinline__ void ldm4t(uint32_t* r, uint32_t addr) {
    asm volatile("ldmatrix.sync.aligned.m8n8.x4.trans.shared.b16 {%0,%1,%2,%3}, [%4];"
        : "=r"(r[0]), "=r"(r[1]), "=r"(r[2]), "=r"(r[3]) : "r"(addr));
}
static __device__ __forceinline__ void mma16816(float* d, const uint32_t* a,
                                                uint32_t b0, uint32_t b1) {
    asm volatile(
        "mma.sync.aligned.m16n8k16.row.col.f32.bf16.bf16.f32 "
        "{%0,%1,%2,%3}, {%4,%5,%6,%7}, {%8,%9}, {%0,%1,%2,%3};"
        : "+f"(d[0]), "+f"(d[1]), "+f"(d[2]), "+f"(d[3])
        : "r"(a[0]), "r"(a[1]), "r"(a[2]), "r"(a[3]), "r"(b0), "r"(b1));
}
static __device__ __forceinline__ uint32_t pack2(__nv_bfloat16 a, __nv_bfloat16 b) {
    __nv_bfloat162 t(a, b);
    return *(uint32_t*)&t;
}
static __device__ __forceinline__ void split2(float a, float b,
                                              uint32_t& h, uint32_t& l) {
    __nv_bfloat16 ha = __float2bfloat16(a), hb = __float2bfloat16(b);
    h = pack2(ha, hb);
    l = pack2(__float2bfloat16(a - __bfloat162float(ha)),
              __float2bfloat16(b - __bfloat162float(hb)));
}
static __device__ __forceinline__ void split4(float4 v, uint2& hi, uint2& lo) {
    split2(v.x, v.y, hi.x, lo.x);
    split2(v.z, v.w, hi.y, lo.y);
}
static __device__ __forceinline__ float neg_inf() {
    return __int_as_float(0xff800000);
}

// ================= pre-pass: split float arrays into bf16 hi/lo planes =====
template <int SEL>
__global__ __launch_bounds__(256)
void split_planes(const float* __restrict__ src, int n4)
{
    __nv_bfloat16* h = (SEL == 0) ? g_xh : ((SEL == 1) ? g_wqh : g_wph);
    __nv_bfloat16* l = (SEL == 0) ? g_xl : ((SEL == 1) ? g_wql : g_wpl);
    int i = blockIdx.x * 256 + threadIdx.x;
    if (i < n4) {
        float4 v = ((const float4*)src)[i];
        uint2 hh, ll;
        split4(v, hh, ll);
        ((uint2*)h)[i] = hh;
        ((uint2*)l)[i] = ll;
    }
}

// ================= bf16x3 tensor-core GEMM (cp.async, pre-split planes) ====
#define GBM 128
#define GBN 128
#define GKC 32
#define ROWB 80
#define PLANEB 10240
#define STAGEB 40960
#define SM_STG 1024
#define SMEM_GEMM (SM_STG + 2 * STAGEB)

template <int MODE>
__global__ __launch_bounds__(256, 2)
void gemm_bf16x3(const float* __restrict__ bias,
                 float* __restrict__ Cout,
                 int K, int Nout)
{
    extern __shared__ char smem[];
    float* sbias = (float*)smem;
    char* stg = smem + SM_STG;
    const uint32_t su = smem_u32(stg);

    const int tid = threadIdx.x;
    const int wid = tid >> 5, lane = tid & 31;
    const int m0 = blockIdx.y * GBM, n0 = blockIdx.x * GBN;
    const int NC = K / GKC;
    const int wm = (wid & 1) * 64;
    const int wn = (wid >> 1) * 32;

    if (tid < GBN) sbias[tid] = bias[n0 + tid];

    const __nv_bfloat16* pb[4];
    if (MODE == 0) {
        pb[0] = g_xh  + (size_t)m0 * K;
        pb[1] = g_xl  + (size_t)m0 * K;
        pb[2] = g_wqh + (size_t)n0 * K;
        pb[3] = g_wql + (size_t)n0 * K;
    } else {
        pb[0] = g_atth + (size_t)m0 * K;
        pb[1] = g_attl + (size_t)m0 * K;
        pb[2] = g_wph  + (size_t)n0 * K;
        pb[3] = g_wpl  + (size_t)n0 * K;
    }

    const int r0  = tid >> 2;
    const int c16 = tid & 3;

    auto issue = [&](int kc, int s) {
        uint32_t sb = su + s * STAGEB;
#pragma unroll
        for (int p = 0; p < 4; p++) {
#pragma unroll
            for (int hh = 0; hh < 2; hh++) {
                int r = r0 + hh * 64;
                const void* src = pb[p] + (size_t)r * K + kc + c16 * 8;
                uint32_t dst = sb + p * PLANEB + r * ROWB + c16 * 16;
                cp16(dst, src);
            }
        }
        asm volatile("cp.async.commit_group;" ::: "memory");
    };

    float acc[4][4][4];
#pragma unroll
    for (int i = 0; i < 4; i++)
#pragma unroll
        for (int j = 0; j < 4; j++)
#pragma unroll
            for (int q = 0; q < 4; q++) acc[i][j][q] = 0.0f;

    issue(0, 0);
    issue(GKC, 1);

    const uint32_t a_lrow_off = (uint32_t)(wm + (lane & 15)) * ROWB
                              + ((lane >> 4) << 4);
    const uint32_t b_lrow_off = (uint32_t)(wn + ((lane >> 4) << 3) + (lane & 7)) * ROWB
                              + (((lane >> 3) & 1) << 4);

    for (int c = 0; c < NC; c++) {
        if (c + 1 < NC)
            asm volatile("cp.async.wait_group 1;" ::: "memory");
        else
            asm volatile("cp.async.wait_group 0;" ::: "memory");
        __syncthreads();

        const uint32_t sb = su + (c & 1) * STAGEB;

#pragma unroll
        for (int ks = 0; ks < 2; ks++) {
            uint32_t ah[4][4], al[4][4];
            uint32_t bh[4][2], bl[4][2];
#pragma unroll
            for (int mt = 0; mt < 4; mt++) {
                uint32_t ad = sb + a_lrow_off + (uint32_t)(mt * 16) * ROWB + ks * 32;
                ldm4(ah[mt], ad + 0 * PLANEB);
                ldm4(al[mt], ad + 1 * PLANEB);
            }
#pragma unroll
            for (int p = 0; p < 2; p++) {
                uint32_t bd = sb + b_lrow_off + (uint32_t)(p * 16) * ROWB + ks * 32;
                uint32_t t[4];
                ldm4(t, bd + 2 * PLANEB);
                bh[2*p][0] = t[0]; bh[2*p][1] = t[1];
                bh[2*p+1][0] = t[2]; bh[2*p+1][1] = t[3];
                ldm4(t, bd + 3 * PLANEB);
                bl[2*p][0] = t[0]; bl[2*p][1] = t[1];
                bl[2*p+1][0] = t[2]; bl[2*p+1][1] = t[3];
            }
#pragma unroll
            for (int mt = 0; mt < 4; mt++)
#pragma unroll
                for (int nt = 0; nt < 4; nt++) {
                    mma16816(acc[mt][nt], ah[mt], bh[nt][0], bh[nt][1]);
                    mma16816(acc[mt][nt], ah[mt], bl[nt][0], bl[nt][1]);
                    mma16816(acc[mt][nt], al[mt], bh[nt][0], bh[nt][1]);
                }
        }
        __syncthreads();
        if (c + 2 < NC) issue((c + 2) * GKC, c & 1);
    }

    // epilogue
    const int t  = n0 >> 10;           // MODE 0: q/k/v select
    const int hd = (n0 & 1023) >> 7;
    __nv_bfloat16* dh = (t == 0) ? g_qh : ((t == 1) ? g_kh : g_vh);
    __nv_bfloat16* dl = (t == 0) ? g_ql : ((t == 1) ? g_kl : g_vl);
    const float sc = (t == 0) ? (1.0f / 32.0f) : 1.0f;   // fold softmax scale into q

#pragma unroll
    for (int mt = 0; mt < 4; mt++) {
#pragma unroll
        for (int nt = 0; nt < 4; nt++) {
            float* d = acc[mt][nt];
            int rr = wm + mt * 16 + (lane >> 2);
            int cc = wn + nt * 8 + (lane & 3) * 2;
            float bb0 = sbias[cc], bb1 = sbias[cc + 1];
            int m1 = m0 + rr, m2 = m1 + 8;
            if (MODE == 0) {
                int b1i = m1 >> 11, nn1 = m1 & 2047;
                size_t o1 = (((size_t)(b1i * HH + hd)) * NSEQ + nn1) * DH + cc;
                uint32_t h, l;
                split2((d[0] + bb0) * sc, (d[1] + bb1) * sc, h, l);
                *(uint32_t*)&dh[o1] = h; *(uint32_t*)&dl[o1] = l;
                int b2i = m2 >> 11, nn2 = m2 & 2047;
                size_t o2 = (((size_t)(b2i * HH + hd)) * NSEQ + nn2) * DH + cc;
                split2((d[2] + bb0) * sc, (d[3] + bb1) * sc, h, l);
                *(uint32_t*)&dh[o2] = h; *(uint32_t*)&dl[o2] = l;
            } else {
                float2* p1 = (float2*)(Cout + (size_t)m1 * Nout + n0 + cc);
                *p1 = make_float2(d[0] + bb0, d[1] + bb1);
                float2* p2 = (float2*)(Cout + (size_t)m2 * Nout + n0 + cc);
                *p2 = make_float2(d[2] + bb0, d[3] + bb1);
            }
        }
    }
}

// ================= windowed flash attention — tensor core =================
// CTA: 64 q-rows, one (b,h); 256 threads = 8 warps.
#define AQ_B  272           // Q/K/V smem row stride bytes (128 bf16 + pad)
#define AP_B  144           // P smem row stride bytes (64 bf16 + pad)
#define AS_W  68            // Sf row stride (fp32 words)
#define O_QH   0
#define O_QL   17408
#define O_KV   34816        // stage base; per-stage: KH,KL,VH,VL
#define KV_STG 69632
#define OK_H   0
#define OK_L   17408
#define OV_H   34816
#define OV_L   52224
#define O_SF   174080
#define O_PH   191488
#define O_PL   200704
#define O_CORR 209920
#define O_LSUM 210176
#define SMEM_ATTN 210432

__global__ __launch_bounds__(256)
void attn_win()
{
    extern __shared__ char smem[];
    const uint32_t su = smem_u32(smem);
    const int tid = threadIdx.x;
    const int lane = tid & 31, wid = tid >> 5;
    const int q0 = blockIdx.x * 64;
    const int bh = blockIdx.y;
    const size_t base = (size_t)bh * NSEQ * DH;
    const float NEGINF = neg_inf();

    // ---- Q tile (hi/lo) via cp.async ----
    {
        int row = tid >> 4, ck = tid & 15;
#pragma unroll
        for (int it = 0; it < 4; it++) {
            int r = row + it * 16;
            size_t go = base + (size_t)(q0 + r) * DH + ck * 8;
            cp16(su + O_QH + r * AQ_B + ck * 16, g_qh + go);
            cp16(su + O_QL + r * AQ_B + ck * 16, g_ql + go);
        }
        asm volatile("cp.async.commit_group;" ::: "memory");
    }

    int lo = q0 - (HALFW - 1); if (lo < 0) lo = 0;
    int hi = q0 + 63 + (HALFW - 1); if (hi > NSEQ - 1) hi = NSEQ - 1;
    const int kt0 = lo & ~63;
    const int ntiles = ((hi - kt0) >> 6) + 1;

    auto load_kv = [&](int t, int s) {
        int kt = kt0 + t * 64;
        uint32_t sb = su + O_KV + s * KV_STG;
        int row = tid >> 4, ck = tid & 15;
#pragma unroll
        for (int it = 0; it < 4; it++) {
            int r = row + it * 16;
            size_t go = base + (size_t)(kt + r) * DH + ck * 8;
            uint32_t d = r * AQ_B + ck * 16;
            cp16(sb + OK_H + d, g_kh + go);
            cp16(sb + OK_L + d, g_kl + go);
            cp16(sb + OV_H + d, g_vh + go);
            cp16(sb + OV_L + d, g_vl + go);
        }
        asm volatile("cp.async.commit_group;" ::: "memory");
    };
    load_kv(0, 0);

    // warp coords: phase A (4q x 2k), phase C (4q x 2d)
    const int wq = wid >> 1;
    const int wk = wid & 1;
    const uint32_t aq_off = (uint32_t)(wq * 16 + (lane & 15)) * AQ_B
                          + ((lane >> 4) << 4);
    const uint32_t bk_off = (uint32_t)(wk * 32 + ((lane >> 4) << 3) + (lane & 7)) * AQ_B
                          + (((lane >> 3) & 1) << 4);
    const uint32_t ap_off = (uint32_t)(wq * 16 + (lane & 15)) * AP_B
                          + ((lane >> 4) << 4);
    const uint32_t bv_row = (lane & 7) + ((lane >> 3) & 1) * 8;
    const uint32_t bv_c16 = ((lane >> 4) << 4);

    // phase-B identities
    const int tx = tid & 15, ty = tid >> 4;
    float mrow[4], lsum[4];
#pragma unroll
    for (int i = 0; i < 4; i++) { mrow[i] = NEGINF; lsum[i] = 0.0f; }

    float oacc[4][2][4];
#pragma unroll
    for (int a = 0; a < 4; a++)
#pragma unroll
        for (int b = 0; b < 2; b++)
#pragma unroll
            for (int q = 0; q < 4; q++) oacc[a][b][q] = 0.0f;

    float* Sf = (float*)(smem + O_SF);
    float* scorr = (float*)(smem + O_CORR);
    float* slsum = (float*)(smem + O_LSUM);

    for (int t = 0; t < ntiles; t++) {
        const int s = t & 1;
        const uint32_t kvb = su + O_KV + s * KV_STG;

        __syncthreads();                         // prev PV done reading buf s^1
        if (t + 1 < ntiles) {
            load_kv(t + 1, s ^ 1);
            asm volatile("cp.async.wait_group 1;" ::: "memory");
        } else {
            asm volatile("cp.async.wait_group 0;" ::: "memory");
        }
        __syncthreads();

        // ---- phase A: S = Q K^T (3-term bf16) ----
        float sacc[4][4];
#pragma unroll
        for (int nt = 0; nt < 4; nt++)
#pragma unroll
            for (int q = 0; q < 4; q++) sacc[nt][q] = 0.0f;

#pragma unroll
        for (int ks = 0; ks < 8; ks++) {
            uint32_t ah[4], al[4];
            ldm4(ah, su + O_QH + aq_off + ks * 32);
            ldm4(al, su + O_QL + aq_off + ks * 32);
            uint32_t bhf[4][2], blf[4][2];
#pragma unroll
            for (int p = 0; p < 2; p++) {
                uint32_t bd = kvb + bk_off + (uint32_t)(p * 16) * AQ_B + ks * 32;
                uint32_t tt[4];
                ldm4(tt, bd + OK_H);
                bhf[2*p][0] = tt[0]; bhf[2*p][1] = tt[1];
                bhf[2*p+1][0] = tt[2]; bhf[2*p+1][1] = tt[3];
                ldm4(tt, bd + OK_L);
                blf[2*p][0] = tt[0]; blf[2*p][1] = tt[1];
                blf[2*p+1][0] = tt[2]; blf[2*p+1][1] = tt[3];
            }
#pragma unroll
            for (int nt = 0; nt < 4; nt++) {
                mma16816(sacc[nt], ah, bhf[nt][0], bhf[nt][1]);
                mma16816(sacc[nt], ah, blf[nt][0], blf[nt][1]);
                mma16816(sacc[nt], al, bhf[nt][0], bhf[nt][1]);
            }
        }
        // store S fragments
        {
            int r1 = wq * 16 + (lane >> 2);
            int cb = wk * 32 + (lane & 3) * 2;
#pragma unroll
            for (int nt = 0; nt < 4; nt++) {
                float* p1 = Sf + r1 * AS_W + cb + nt * 8;
                p1[0] = sacc[nt][0]; p1[1] = sacc[nt][1];
                float* p2 = p1 + 8 * AS_W;
                p2[0] = sacc[nt][2]; p2[1] = sacc[nt][3];
            }
        }
        __syncthreads();

        // ---- phase B: online softmax, P -> bf16 hi/lo planes ----
        const int kt = kt0 + t * 64;
#pragma unroll
        for (int i = 0; i < 4; i++) {
            int row = ty * 4 + i;
            int qg = q0 + row;
            float4 sv = *(float4*)(Sf + row * AS_W + tx * 4);
            float sA[4] = {sv.x, sv.y, sv.z, sv.w};
#pragma unroll
            for (int j = 0; j < 4; j++) {
                int jg = kt + tx * 4 + j;
                int d = qg - jg; if (d < 0) d = -d;
                if (d >= HALFW) sA[j] = NEGINF;
            }
            float rm = fmaxf(fmaxf(sA[0], sA[1]), fmaxf(sA[2], sA[3]));
            rm = fmaxf(rm, __shfl_xor_sync(0xffffffffu, rm, 1));
            rm = fmaxf(rm, __shfl_xor_sync(0xffffffffu, rm, 2));
            rm = fmaxf(rm, __shfl_xor_sync(0xffffffffu, rm, 4));
            rm = fmaxf(rm, __shfl_xor_sync(0xffffffffu, rm, 8));
            float mnew = fmaxf(mrow[i], rm);
            float corr, p[4];
            if (mnew == NEGINF) {
                corr = 1.0f;
                p[0] = p[1] = p[2] = p[3] = 0.0f;
            } else {
                corr = __expf(mrow[i] - mnew);
#pragma unroll
                for (int j = 0; j < 4; j++) p[j] = __expf(sA[j] - mnew);
            }
            float rs = (p[0] + p[1]) + (p[2] + p[3]);
            rs += __shfl_xor_sync(0xffffffffu, rs, 1);
            rs += __shfl_xor_sync(0xffffffffu, rs, 2);
            rs += __shfl_xor_sync(0xffffffffu, rs, 4);
            rs += __shfl_xor_sync(0xffffffffu, rs, 8);
            lsum[i] = lsum[i] * corr + rs;
            mrow[i] = mnew;
            uint32_t h01, l01, h23, l23;
            split2(p[0], p[1], h01, l01);
            split2(p[2], p[3], h23, l23);
            *(uint2*)((char*)smem + O_PH + row * AP_B + tx * 8) = make_uint2(h01, h23);
            *(uint2*)((char*)smem + O_PL + row * AP_B + tx * 8) = make_uint2(l01, l23);
            if (tx == 0) scorr[row] = corr;
        }
        __syncthreads();

        // ---- phase C: O = corr*O + P V (3-term bf16) ----
        {
            int r1 = wq * 16 + (lane >> 2);
            float c1 = scorr[r1], c2 = scorr[r1 + 8];
#pragma unroll
            for (int a = 0; a < 4; a++)
#pragma unroll
                for (int b = 0; b < 2; b++) {
                    oacc[a][b][0] *= c1; oacc[a][b][1] *= c1;
                    oacc[a][b][2] *= c2; oacc[a][b][3] *= c2;
                }
#pragma unroll
            for (int kk = 0; kk < 4; kk++) {
                uint32_t ah[4], al[4];
                ldm4(ah, su + O_PH + ap_off + kk * 32);
                ldm4(al, su + O_PL + ap_off + kk * 32);
#pragma unroll
                for (int t16 = 0; t16 < 4; t16++) {
                    uint32_t va = kvb + (uint32_t)(kk * 16 + bv_row) * AQ_B
                                + (uint32_t)(wk * 64 + t16 * 16) * 2 + bv_c16;
                    uint32_t vh[4], vl[4];
                    ldm4t(vh, va + OV_H);
                    ldm4t(vl, va + OV_L);
                    mma16816(oacc[t16][0], ah, vh[0], vh[1]);
                    mma16816(oacc[t16][0], ah, vl[0], vl[1]);
                    mma16816(oacc[t16][0], al, vh[0], vh[1]);
                    mma16816(oacc[t16][1], ah, vh[2], vh[3]);
                    mma16816(oacc[t16][1], ah, vl[2], vl[3]);
                    mma16816(oacc[t16][1], al, vh[2], vh[3]);
                }
            }
        }
    }

    // ---- epilogue: normalize, write att hi/lo planes ----
#pragma unroll
    for (int i = 0; i < 4; i++)
        if (tx == 0) slsum[ty * 4 + i] = lsum[i];
    __syncthreads();
    {
        int r1 = wq * 16 + (lane >> 2), r2 = r1 + 8;
        float inv1 = 1.0f / slsum[r1];
        float inv2 = 1.0f / slsum[r2];
        const int b = bh >> 3, h = bh & 7;
        size_t ob1 = ((size_t)b * NSEQ + (q0 + r1)) * CDIM + h * DH;
        size_t ob2 = ((size_t)b * NSEQ + (q0 + r2)) * CDIM + h * DH;
#pragma unroll
        for (int t16 = 0; t16 < 4; t16++)
#pragma unroll
            for (int hf = 0; hf < 2; hf++) {
                int c = wk * 64 + t16 * 16 + hf * 8 + (lane & 3) * 2;
                float* d = oacc[t16][hf];
                uint32_t hh, ll;
                split2(d[0] * inv1, d[1] * inv1, hh, ll);
                *(uint32_t*)&g_atth[ob1 + c] = hh;
                *(uint32_t*)&g_attl[ob1 + c] = ll;
                split2(d[2] * inv2, d[3] * inv2, hh, ll);
                *(uint32_t*)&g_atth[ob2 + c] = hh;
                *(uint32_t*)&g_attl[ob2 + c] = ll;
            }
    }
}

// ---------------- launch ----------------
extern "C" void kernel_launch(void* const* d_in, const int* in_sizes, int n_in,
                              void* d_out, int out_size)
{
    const float* x      = (const float*)d_in[0];
    const float* w_qkv  = (const float*)d_in[1];
    const float* b_qkv  = (const float*)d_in[2];
    const float* w_proj = (const float*)d_in[3];
    const float* b_proj = (const float*)d_in[4];
    float* out = (float*)d_out;

    cudaFuncSetAttribute(gemm_bf16x3<0>,
                         cudaFuncAttributeMaxDynamicSharedMemorySize, SMEM_GEMM);
    cudaFuncSetAttribute(gemm_bf16x3<1>,
                         cudaFuncAttributeMaxDynamicSharedMemorySize, SMEM_GEMM);
    cudaFuncSetAttribute(attn_win,
                         cudaFuncAttributeMaxDynamicSharedMemorySize, SMEM_ATTN);

    // 0) split inputs into bf16 hi/lo planes
    {
        int n4x = (Bb * NSEQ * CDIM) / 4;
        int n4q = (3 * CDIM * CDIM) / 4;
        int n4p = (CDIM * CDIM) / 4;
        split_planes<0><<<(n4x + 255) / 256, 256>>>(x, n4x);
        split_planes<1><<<(n4q + 255) / 256, 256>>>(w_qkv, n4q);
        split_planes<2><<<(n4p + 255) / 256, 256>>>(w_proj, n4p);
    }

    // 1) QKV projection -> q/k/v bf16 hi/lo planes [B,H,N,D] (q pre-scaled)
    dim3 g1((3 * CDIM) / GBN, (Bb * NSEQ) / GBM);   // (24, 32)
    gemm_bf16x3<0><<<g1, 256, SMEM_GEMM>>>(b_qkv, nullptr, CDIM, 3 * CDIM);

    // 2) banded attention (tensor core) -> g_atth/g_attl planes
    dim3 g2(NSEQ / 64, Bb * HH);                    // (32, 16)
    attn_win<<<g2, 256, SMEM_ATTN>>>();

    // 3) output projection
    dim3 g3(CDIM / GBN, (Bb * NSEQ) / GBM);         // (8, 32)
    gemm_bf16x3<1><<<g3, 256, SMEM_GEMM>>>(b_proj, out, CDIM, CDIM);
}

// round 14
// speedup vs baseline: 2.6916x; 1.0122x over previous
#include <cuda_runtime.h>
#include <cuda_bf16.h>
#include <math.h>
#include <stdint.h>

// Problem constants
#define Bb    2
#define NSEQ  2048
#define CDIM  1024
#define HH    8
#define DH    128
#define HALFW 128   // WS/2

// bf16 hi/lo planes (device globals — no allocation allowed)
__device__ __nv_bfloat16 g_xh[Bb*NSEQ*CDIM],  g_xl[Bb*NSEQ*CDIM];
__device__ __nv_bfloat16 g_wqh[3*CDIM*CDIM],  g_wql[3*CDIM*CDIM];
__device__ __nv_bfloat16 g_wph[CDIM*CDIM],    g_wpl[CDIM*CDIM];
__device__ __nv_bfloat16 g_atth[Bb*NSEQ*CDIM], g_attl[Bb*NSEQ*CDIM];
// q/k/v planes, [B,H,N,D]; q pre-scaled by 1/32
__device__ __nv_bfloat16 g_qh[Bb*HH*NSEQ*DH], g_ql[Bb*HH*NSEQ*DH];
__device__ __nv_bfloat16 g_kh[Bb*HH*NSEQ*DH], g_kl[Bb*HH*NSEQ*DH];
__device__ __nv_bfloat16 g_vh[Bb*HH*NSEQ*DH], g_vl[Bb*HH*NSEQ*DH];

// ================= helpers =================
static __device__ __forceinline__ uint32_t smem_u32(const void* p) {
    uint32_t a;
    asm("{ .reg .u64 t; cvta.to.shared.u64 t, %1; cvt.u32.u64 %0, t; }"
        : "=r"(a) : "l"(p));
    return a;
}
static __device__ __forceinline__ void cp16(uint32_t dst, const void* src) {
    asm volatile("cp.async.cg.shared.global [%0], [%1], 16;"
                 :: "r"(dst), "l"(src));
}
static __device__ __forceinline__ void ldm4(uint32_t* r, uint32_t addr) {
    asm volatile("ldmatrix.sync.aligned.m8n8.x4.shared.b16 {%0,%1,%2,%3}, [%4];"
        : "=r"(r[0]), "=r"(r[1]), "=r"(r[2]), "=r"(r[3]) : "r"(addr));
}
static __device__ __forceinline__ void ldm4t(uint32_t* r, uint32_t addr) {
    asm volatile("ldmatrix.sync.aligned.m8n8.x4.trans.shared.b16 {%0,%1,%2,%3}, [%4];"
        : "=r"(r[0]), "=r"(r[1]), "=r"(r[2]), "=r"(r[3]) : "r"(addr));
}
static __device__ __forceinline__ void mma16816(float* d, const uint32_t* a,
                                                uint32_t b0, uint32_t b1) {
    asm volatile(
        "mma.sync.aligned.m16n8k16.row.col.f32.bf16.bf16.f32 "
        "{%0,%1,%2,%3}, {%4,%5,%6,%7}, {%8,%9}, {%0,%1,%2,%3};"
        : "+f"(d[0]), "+f"(d[1]), "+f"(d[2]), "+f"(d[3])
        : "r"(a[0]), "r"(a[1]), "r"(a[2]), "r"(a[3]), "r"(b0), "r"(b1));
}
static __device__ __forceinline__ uint32_t pack2(__nv_bfloat16 a, __nv_bfloat16 b) {
    __nv_bfloat162 t(a, b);
    return *(uint32_t*)&t;
}
static __device__ __forceinline__ void split2(float a, float b,
                                              uint32_t& h, uint32_t& l) {
    __nv_bfloat16 ha = __float2bfloat16(a), hb = __float2bfloat16(b);
    h = pack2(ha, hb);
    l = pack2(__float2bfloat16(a - __bfloat162float(ha)),
              __float2bfloat16(b - __bfloat162float(hb)));
}
static __device__ __forceinline__ void split4(float4 v, uint2& hi, uint2& lo) {
    split2(v.x, v.y, hi.x, lo.x);
    split2(v.z, v.w, hi.y, lo.y);
}
static __device__ __forceinline__ float neg_inf() {
    return __int_as_float(0xff800000);
}

// ================= fused pre-pass: split all inputs into hi/lo planes ======
#define N4X (Bb*NSEQ*CDIM/4)     // 1048576
#define N4Q (3*CDIM*CDIM/4)      //  786432
#define N4P (CDIM*CDIM/4)        //  262144

__global__ __launch_bounds__(256)
void split_all(const float* __restrict__ x,
               const float* __restrict__ wq,
               const float* __restrict__ wp)
{
    int i = blockIdx.x * 256 + threadIdx.x;
    const float* src;
    __nv_bfloat16 *h, *l;
    int j;
    if (i < N4X) {
        src = x; h = g_xh; l = g_xl; j = i;
    } else if (i < N4X + N4Q) {
        src = wq; h = g_wqh; l = g_wql; j = i - N4X;
    } else {
        src = wp; h = g_wph; l = g_wpl; j = i - N4X - N4Q;
    }
    float4 v = ((const float4*)src)[j];
    uint2 hh, ll;
    split4(v, hh, ll);
    ((uint2*)h)[j] = hh;
    ((uint2*)l)[j] = ll;
}

// ================= bf16x3 tensor-core GEMM — 3-stage cp.async =============
// C[M,Nout] = A[M,K] * B[Nout,K]^T + bias
// Tile 256x128, 512 threads (16 warps, 4x4 warp grid, warp tile 64x32)
#define GBM 256
#define GBN 128
#define GKC 32
#define ROWB 80
#define OFF_AH 0
#define OFF_AL 20480
#define OFF_BH 40960
#define OFF_BL 51200
#define STAGEB 61440
#define SM_STG 1024
#define SMEM_GEMM (SM_STG + 3 * STAGEB)   // 185344

template <int MODE>
__global__ __launch_bounds__(512, 1)
void gemm_bf16x3(const float* __restrict__ bias,
                 float* __restrict__ Cout,
                 int K, int Nout)
{
    extern __shared__ char smem[];
    float* sbias = (float*)smem;
    char* stg = smem + SM_STG;
    const uint32_t su = smem_u32(stg);

    const int tid = threadIdx.x;
    const int wid = tid >> 5, lane = tid & 31;
    const int m0 = blockIdx.y * GBM, n0 = blockIdx.x * GBN;
    const int NC = K / GKC;
    const int wm = (wid & 3) * 64;        // 4 row-groups
    const int wn = (wid >> 2) * 32;       // 4 col-groups

    if (tid < GBN) sbias[tid] = bias[n0 + tid];

    const __nv_bfloat16* pb[4];
    if (MODE == 0) {
        pb[0] = g_xh  + (size_t)m0 * K;
        pb[1] = g_xl  + (size_t)m0 * K;
        pb[2] = g_wqh + (size_t)n0 * K;
        pb[3] = g_wql + (size_t)n0 * K;
    } else {
        pb[0] = g_atth + (size_t)m0 * K;
        pb[1] = g_attl + (size_t)m0 * K;
        pb[2] = g_wph  + (size_t)n0 * K;
        pb[3] = g_wpl  + (size_t)n0 * K;
    }

    const int rA  = tid >> 2;     // 0..127
    const int c16 = tid & 3;

    auto issue = [&](int kc, int s) {
        uint32_t sb = su + s * STAGEB;
#pragma unroll
        for (int hh = 0; hh < 2; hh++) {        // A: rows rA, rA+128
            int r = rA + hh * 128;
            size_t go = (size_t)r * K + kc + c16 * 8;
            uint32_t d = (uint32_t)r * ROWB + c16 * 16;
            cp16(sb + OFF_AH + d, pb[0] + go);
            cp16(sb + OFF_AL + d, pb[1] + go);
        }
        {                                        // B: row rA (0..127)
            size_t go = (size_t)rA * K + kc + c16 * 8;
            uint32_t d = (uint32_t)rA * ROWB + c16 * 16;
            cp16(sb + OFF_BH + d, pb[2] + go);
            cp16(sb + OFF_BL + d, pb[3] + go);
        }
        asm volatile("cp.async.commit_group;" ::: "memory");
    };

    float acc[4][4][4];
#pragma unroll
    for (int i = 0; i < 4; i++)
#pragma unroll
        for (int j = 0; j < 4; j++)
#pragma unroll
            for (int q = 0; q < 4; q++) acc[i][j][q] = 0.0f;

    issue(0, 0);
    issue(GKC, 1);

    const uint32_t a_lrow_off = (uint32_t)(wm + (lane & 15)) * ROWB
                              + ((lane >> 4) << 4);
    const uint32_t b_lrow_off = (uint32_t)(wn + ((lane >> 4) << 3) + (lane & 7)) * ROWB
                              + (((lane >> 3) & 1) << 4);

    int s_c = 0;                 // stage of chunk c
    for (int c = 0; c < NC; c++) {
        if (c + 1 < NC)
            asm volatile("cp.async.wait_group 1;" ::: "memory");
        else
            asm volatile("cp.async.wait_group 0;" ::: "memory");
        __syncthreads();

        // loads for chunk c+2 -> stage (s_c+2)%3 (no reader conflicts: that
        // stage was consumed in iteration c-1, which all warps completed)
        if (c + 2 < NC) {
            int s2 = s_c + 2; if (s2 >= 3) s2 -= 3;
            issue((c + 2) * GKC, s2);
        }

        const uint32_t sb = su + s_c * STAGEB;
#pragma unroll
        for (int ks = 0; ks < 2; ks++) {
            uint32_t ah[4][4], al[4][4];
            uint32_t bh[4][2], bl[4][2];
#pragma unroll
            for (int mt = 0; mt < 4; mt++) {
                uint32_t ad = sb + a_lrow_off + (uint32_t)(mt * 16) * ROWB + ks * 32;
                ldm4(ah[mt], ad + OFF_AH);
                ldm4(al[mt], ad + OFF_AL);
            }
#pragma unroll
            for (int p = 0; p < 2; p++) {
                uint32_t bd = sb + b_lrow_off + (uint32_t)(p * 16) * ROWB + ks * 32;
                uint32_t t[4];
                ldm4(t, bd + OFF_BH);
                bh[2*p][0] = t[0]; bh[2*p][1] = t[1];
                bh[2*p+1][0] = t[2]; bh[2*p+1][1] = t[3];
                ldm4(t, bd + OFF_BL);
                bl[2*p][0] = t[0]; bl[2*p][1] = t[1];
                bl[2*p+1][0] = t[2]; bl[2*p+1][1] = t[3];
            }
#pragma unroll
            for (int mt = 0; mt < 4; mt++)
#pragma unroll
                for (int nt = 0; nt < 4; nt++) {
                    mma16816(acc[mt][nt], ah[mt], bh[nt][0], bh[nt][1]);
                    mma16816(acc[mt][nt], ah[mt], bl[nt][0], bl[nt][1]);
                    mma16816(acc[mt][nt], al[mt], bh[nt][0], bh[nt][1]);
                }
        }
        if (++s_c == 3) s_c = 0;
    }

    // epilogue
    const int t  = n0 >> 10;           // MODE 0: q/k/v select (GBN=128)
    const int hd = (n0 & 1023) >> 7;
    __nv_bfloat16* dh = (t == 0) ? g_qh : ((t == 1) ? g_kh : g_vh);
    __nv_bfloat16* dl = (t == 0) ? g_ql : ((t == 1) ? g_kl : g_vl);
    const float sc = (t == 0) ? (1.0f / 32.0f) : 1.0f;

#pragma unroll
    for (int mt = 0; mt < 4; mt++) {
#pragma unroll
        for (int nt = 0; nt < 4; nt++) {
            float* d = acc[mt][nt];
            int rr = wm + mt * 16 + (lane >> 2);
            int cc = wn + nt * 8 + (lane & 3) * 2;
            float bb0 = sbias[cc], bb1 = sbias[cc + 1];
            int m1 = m0 + rr, m2 = m1 + 8;
            if (MODE == 0) {
                int b1i = m1 >> 11, nn1 = m1 & 2047;
                size_t o1 = (((size_t)(b1i * HH + hd)) * NSEQ + nn1) * DH + cc;
                uint32_t h, l;
                split2((d[0] + bb0) * sc, (d[1] + bb1) * sc, h, l);
                *(uint32_t*)&dh[o1] = h; *(uint32_t*)&dl[o1] = l;
                int b2i = m2 >> 11, nn2 = m2 & 2047;
                size_t o2 = (((size_t)(b2i * HH + hd)) * NSEQ + nn2) * DH + cc;
                split2((d[2] + bb0) * sc, (d[3] + bb1) * sc, h, l);
                *(uint32_t*)&dh[o2] = h; *(uint32_t*)&dl[o2] = l;
            } else {
                float2* p1 = (float2*)(Cout + (size_t)m1 * Nout + n0 + cc);
                *p1 = make_float2(d[0] + bb0, d[1] + bb1);
                float2* p2 = (float2*)(Cout + (size_t)m2 * Nout + n0 + cc);
                *p2 = make_float2(d[2] + bb0, d[3] + bb1);
            }
        }
    }
}

// ================= windowed flash attention — tensor core =================
// CTA: 64 q-rows, one (b,h); 256 threads = 8 warps.
#define AQ_B  272
#define AP_B  144
#define AS_W  68
#define O_QH   0
#define O_QL   17408
#define O_KV   34816
#define KV_STG 69632
#define OK_H   0
#define OK_L   17408
#define OV_H   34816
#define OV_L   52224
#define O_SF   174080
#define O_PH   191488
#define O_PL   200704
#define O_CORR 209920
#define O_LSUM 210176
#define SMEM_ATTN 210432

__global__ __launch_bounds__(256)
void attn_win()
{
    extern __shared__ char smem[];
    const uint32_t su = smem_u32(smem);
    const int tid = threadIdx.x;
    const int lane = tid & 31, wid = tid >> 5;
    const int q0 = blockIdx.x * 64;
    const int bh = blockIdx.y;
    const size_t base = (size_t)bh * NSEQ * DH;
    const float NEGINF = neg_inf();

    // ---- Q tile (hi/lo) via cp.async ----
    {
        int row = tid >> 4, ck = tid & 15;
#pragma unroll
        for (int it = 0; it < 4; it++) {
            int r = row + it * 16;
            size_t go = base + (size_t)(q0 + r) * DH + ck * 8;
            cp16(su + O_QH + r * AQ_B + ck * 16, g_qh + go);
            cp16(su + O_QL + r * AQ_B + ck * 16, g_ql + go);
        }
        asm volatile("cp.async.commit_group;" ::: "memory");
    }

    int lo = q0 - (HALFW - 1); if (lo < 0) lo = 0;
    int hi = q0 + 63 + (HALFW - 1); if (hi > NSEQ - 1) hi = NSEQ - 1;
    const int kt0 = lo & ~63;
    const int ntiles = ((hi - kt0) >> 6) + 1;

    auto load_kv = [&](int t, int s) {
        int kt = kt0 + t * 64;
        uint32_t sb = su + O_KV + s * KV_STG;
        int row = tid >> 4, ck = tid & 15;
#pragma unroll
        for (int it = 0; it < 4; it++) {
            int r = row + it * 16;
            size_t go = base + (size_t)(kt + r) * DH + ck * 8;
            uint32_t d = r * AQ_B + ck * 16;
            cp16(sb + OK_H + d, g_kh + go);
            cp16(sb + OK_L + d, g_kl + go);
            cp16(sb + OV_H + d, g_vh + go);
            cp16(sb + OV_L + d, g_vl + go);
        }
        asm volatile("cp.async.commit_group;" ::: "memory");
    };
    load_kv(0, 0);

    const int wq = wid >> 1;
    const int wk = wid & 1;
    const uint32_t aq_off = (uint32_t)(wq * 16 + (lane & 15)) * AQ_B
                          + ((lane >> 4) << 4);
    const uint32_t bk_off = (uint32_t)(wk * 32 + ((lane >> 4) << 3) + (lane & 7)) * AQ_B
                          + (((lane >> 3) & 1) << 4);
    const uint32_t ap_off = (uint32_t)(wq * 16 + (lane & 15)) * AP_B
                          + ((lane >> 4) << 4);
    const uint32_t bv_row = (lane & 7) + ((lane >> 3) & 1) * 8;
    const uint32_t bv_c16 = ((lane >> 4) << 4);

    const int tx = tid & 15, ty = tid >> 4;
    float mrow[4], lsum[4];
#pragma unroll
    for (int i = 0; i < 4; i++) { mrow[i] = NEGINF; lsum[i] = 0.0f; }

    float oacc[4][2][4];
#pragma unroll
    for (int a = 0; a < 4; a++)
#pragma unroll
        for (int b = 0; b < 2; b++)
#pragma unroll
            for (int q = 0; q < 4; q++) oacc[a][b][q] = 0.0f;

    float* Sf = (float*)(smem + O_SF);
    float* scorr = (float*)(smem + O_CORR);
    float* slsum = (float*)(smem + O_LSUM);

    for (int t = 0; t < ntiles; t++) {
        const int s = t & 1;
        const uint32_t kvb = su + O_KV + s * KV_STG;

        __syncthreads();
        if (t + 1 < ntiles) {
            load_kv(t + 1, s ^ 1);
            asm volatile("cp.async.wait_group 1;" ::: "memory");
        } else {
            asm volatile("cp.async.wait_group 0;" ::: "memory");
        }
        __syncthreads();

        // ---- phase A: S = Q K^T (3-term bf16) ----
        float sacc[4][4];
#pragma unroll
        for (int nt = 0; nt < 4; nt++)
#pragma unroll
            for (int q = 0; q < 4; q++) sacc[nt][q] = 0.0f;

#pragma unroll
        for (int ks = 0; ks < 8; ks++) {
            uint32_t ah[4], al[4];
            ldm4(ah, su + O_QH + aq_off + ks * 32);
            ldm4(al, su + O_QL + aq_off + ks * 32);
            uint32_t bhf[4][2], blf[4][2];
#pragma unroll
            for (int p = 0; p < 2; p++) {
                uint32_t bd = kvb + bk_off + (uint32_t)(p * 16) * AQ_B + ks * 32;
                uint32_t tt[4];
                ldm4(tt, bd + OK_H);
                bhf[2*p][0] = tt[0]; bhf[2*p][1] = tt[1];
                bhf[2*p+1][0] = tt[2]; bhf[2*p+1][1] = tt[3];
                ldm4(tt, bd + OK_L);
                blf[2*p][0] = tt[0]; blf[2*p][1] = tt[1];
                blf[2*p+1][0] = tt[2]; blf[2*p+1][1] = tt[3];
            }
#pragma unroll
            for (int nt = 0; nt < 4; nt++) {
                mma16816(sacc[nt], ah, bhf[nt][0], bhf[nt][1]);
                mma16816(sacc[nt], ah, blf[nt][0], blf[nt][1]);
                mma16816(sacc[nt], al, bhf[nt][0], bhf[nt][1]);
            }
        }
        {
            int r1 = wq * 16 + (lane >> 2);
            int cb = wk * 32 + (lane & 3) * 2;
#pragma unroll
            for (int nt = 0; nt < 4; nt++) {
                float* p1 = Sf + r1 * AS_W + cb + nt * 8;
                p1[0] = sacc[nt][0]; p1[1] = sacc[nt][1];
                float* p2 = p1 + 8 * AS_W;
                p2[0] = sacc[nt][2]; p2[1] = sacc[nt][3];
            }
        }
        __syncthreads();

        // ---- phase B: online softmax, P -> bf16 hi/lo planes ----
        const int kt = kt0 + t * 64;
#pragma unroll
        for (int i = 0; i < 4; i++) {
            int row = ty * 4 + i;
            int qg = q0 + row;
            float4 sv = *(float4*)(Sf + row * AS_W + tx * 4);
            float sA[4] = {sv.x, sv.y, sv.z, sv.w};
#pragma unroll
            for (int j = 0; j < 4; j++) {
                int jg = kt + tx * 4 + j;
                int d = qg - jg; if (d < 0) d = -d;
                if (d >= HALFW) sA[j] = NEGINF;
            }
            float rm = fmaxf(fmaxf(sA[0], sA[1]), fmaxf(sA[2], sA[3]));
            rm = fmaxf(rm, __shfl_xor_sync(0xffffffffu, rm, 1));
            rm = fmaxf(rm, __shfl_xor_sync(0xffffffffu, rm, 2));
            rm = fmaxf(rm, __shfl_xor_sync(0xffffffffu, rm, 4));
            rm = fmaxf(rm, __shfl_xor_sync(0xffffffffu, rm, 8));
            float mnew = fmaxf(mrow[i], rm);
            float corr, p[4];
            if (mnew == NEGINF) {
                corr = 1.0f;
                p[0] = p[1] = p[2] = p[3] = 0.0f;
            } else {
                corr = __expf(mrow[i] - mnew);
#pragma unroll
                for (int j = 0; j < 4; j++) p[j] = __expf(sA[j] - mnew);
            }
            float rs = (p[0] + p[1]) + (p[2] + p[3]);
            rs += __shfl_xor_sync(0xffffffffu, rs, 1);
            rs += __shfl_xor_sync(0xffffffffu, rs, 2);
            rs += __shfl_xor_sync(0xffffffffu, rs, 4);
            rs += __shfl_xor_sync(0xffffffffu, rs, 8);
            lsum[i] = lsum[i] * corr + rs;
            mrow[i] = mnew;
            uint32_t h01, l01, h23, l23;
            split2(p[0], p[1], h01, l01);
            split2(p[2], p[3], h23, l23);
            *(uint2*)((char*)smem + O_PH + row * AP_B + tx * 8) = make_uint2(h01, h23);
            *(uint2*)((char*)smem + O_PL + row * AP_B + tx * 8) = make_uint2(l01, l23);
            if (tx == 0) scorr[row] = corr;
        }
        __syncthreads();

        // ---- phase C: O = corr*O + P V (3-term bf16) ----
        {
            int r1 = wq * 16 + (lane >> 2);
            float c1 = scorr[r1], c2 = scorr[r1 + 8];
#pragma unroll
            for (int a = 0; a < 4; a++)
#pragma unroll
                for (int b = 0; b < 2; b++) {
                    oacc[a][b][0] *= c1; oacc[a][b][1] *= c1;
                    oacc[a][b][2] *= c2; oacc[a][b][3] *= c2;
                }
#pragma unroll
            for (int kk = 0; kk < 4; kk++) {
                uint32_t ah[4], al[4];
                ldm4(ah, su + O_PH + ap_off + kk * 32);
                ldm4(al, su + O_PL + ap_off + kk * 32);
#pragma unroll
                for (int t16 = 0; t16 < 4; t16++) {
                    uint32_t va = kvb + (uint32_t)(kk * 16 + bv_row) * AQ_B
                                + (uint32_t)(wk * 64 + t16 * 16) * 2 + bv_c16;
                    uint32_t vh[4], vl[4];
                    ldm4t(vh, va + OV_H);
                    ldm4t(vl, va + OV_L);
                    mma16816(oacc[t16][0], ah, vh[0], vh[1]);
                    mma16816(oacc[t16][0], ah, vl[0], vl[1]);
                    mma16816(oacc[t16][0], al, vh[0], vh[1]);
                    mma16816(oacc[t16][1], ah, vh[2], vh[3]);
                    mma16816(oacc[t16][1], ah, vl[2], vl[3]);
                    mma16816(oacc[t16][1], al, vh[2], vh[3]);
                }
            }
        }
    }

    // ---- epilogue ----
#pragma unroll
    for (int i = 0; i < 4; i++)
        if (tx == 0) slsum[ty * 4 + i] = lsum[i];
    __syncthreads();
    {
        int r1 = wq * 16 + (lane >> 2), r2 = r1 + 8;
        float inv1 = 1.0f / slsum[r1];
        float inv2 = 1.0f / slsum[r2];
        const int b = bh >> 3, h = bh & 7;
        size_t ob1 = ((size_t)b * NSEQ + (q0 + r1)) * CDIM + h * DH;
        size_t ob2 = ((size_t)b * NSEQ + (q0 + r2)) * CDIM + h * DH;
#pragma unroll
        for (int t16 = 0; t16 < 4; t16++)
#pragma unroll
            for (int hf = 0; hf < 2; hf++) {
                int c = wk * 64 + t16 * 16 + hf * 8 + (lane & 3) * 2;
                float* d = oacc[t16][hf];
                uint32_t hh, ll;
                split2(d[0] * inv1, d[1] * inv1, hh, ll);
                *(uint32_t*)&g_atth[ob1 + c] = hh;
                *(uint32_t*)&g_attl[ob1 + c] = ll;
                split2(d[2] * inv2, d[3] * inv2, hh, ll);
                *(uint32_t*)&g_atth[ob2 + c] = hh;
                *(uint32_t*)&g_attl[ob2 + c] = ll;
            }
    }
}

// ---------------- launch ----------------
extern "C" void kernel_launch(void* const* d_in, const int* in_sizes, int n_in,
                              void* d_out, int out_size)
{
    const float* x      = (const float*)d_in[0];
    const float* w_qkv  = (const float*)d_in[1];
    const float* b_qkv  = (const float*)d_in[2];
    const float* w_proj = (const float*)d_in[3];
    const float* b_proj = (const float*)d_in[4];
    float* out = (float*)d_out;

    cudaFuncSetAttribute(gemm_bf16x3<0>,
                         cudaFuncAttributeMaxDynamicSharedMemorySize, SMEM_GEMM);
    cudaFuncSetAttribute(gemm_bf16x3<1>,
                         cudaFuncAttributeMaxDynamicSharedMemorySize, SMEM_GEMM);
    cudaFuncSetAttribute(attn_win,
                         cudaFuncAttributeMaxDynamicSharedMemorySize, SMEM_ATTN);

    // 0) split all inputs into bf16 hi/lo planes (one fused launch)
    split_all<<<(N4X + N4Q + N4P) / 256, 256>>>(x, w_qkv, w_proj);

    // 1) QKV projection -> q/k/v bf16 hi/lo planes [B,H,N,D] (q pre-scaled)
    dim3 g1((3 * CDIM) / GBN, (Bb * NSEQ) / GBM);   // (24, 16)
    gemm_bf16x3<0><<<g1, 512, SMEM_GEMM>>>(b_qkv, nullptr, CDIM, 3 * CDIM);

    // 2) banded attention (tensor core) -> g_atth/g_attl planes
    dim3 g2(NSEQ / 64, Bb * HH);                    // (32, 16)
    attn_win<<<g2, 256, SMEM_ATTN>>>();

    // 3) output projection
    dim3 g3(CDIM / GBN, (Bb * NSEQ) / GBM);         // (8, 16)
    gemm_bf16x3<1><<<g3, 512, SMEM_GEMM>>>(b_proj, out, CDIM, CDIM);
}